// round 14
// baseline (speedup 1.0000x reference)
#include <cuda_runtime.h>
#include <cuda_bf16.h>
#include <math.h>
#include <stdint.h>

// ---------------- problem constants ----------------
#define L_TXT 256
#define L_IMG 1024
#define L_TMP 1024
#define L_ALL 2304          // txt + img + tmp
#define D_MODEL 1024
#define NH 16
#define HD 64
#define D_MLP 4096
#define EPS 1e-6f
#define ATTN_SCALE 0.125f   // 1/sqrt(64)

// ---------------- scratch (static device memory; no allocation) ----------------
__device__ float g_mod[3 * 6144];
__device__ float g_xm[L_ALL * D_MODEL];        // LN1-modulated, concat order [txt|img|tmp]
__device__ float g_qkv[L_ALL * 3 * D_MODEL];   // QKV gemm out, same row order
__device__ float g_Q[NH * L_ALL * HD];         // tf32-rounded, pre-scaled by ATTN_SCALE
__device__ float g_K[NH * L_ALL * HD];         // tf32-rounded
__device__ float g_V[NH * L_ALL * HD];         // tf32-rounded
__device__ float g_attn[L_ALL * D_MODEL];      // [l][h*64+d], concat order
__device__ float g_x1[L_ALL * D_MODEL];        // post-proj residual, concat order
__device__ float g_ym[1280 * D_MODEL];         // LN2-modulated (img rows 0..1023, txt rows 1024..1279)
__device__ float g_h[1280 * D_MLP];            // MLP hidden

// ---------------- helpers ----------------
__device__ __forceinline__ float gelu_tanh(float x) {
    const float c = 0.7978845608028654f; // sqrt(2/pi)
    float x3 = x * x * x;
    return 0.5f * x * (1.f + tanhf(c * (x + 0.044715f * x3)));
}

__device__ __forceinline__ uint32_t f2tf32(float f) {
    uint32_t u;
    asm("cvt.rna.tf32.f32 %0, %1;" : "=r"(u) : "f"(f));
    return u;
}

__device__ __forceinline__ void mma_tf32(float& d0, float& d1, float& d2, float& d3,
                                         uint32_t a0, uint32_t a1, uint32_t a2, uint32_t a3,
                                         uint32_t b0, uint32_t b1) {
    asm volatile(
        "mma.sync.aligned.m16n8k8.row.col.f32.tf32.tf32.f32 "
        "{%0,%1,%2,%3}, {%4,%5,%6,%7}, {%8,%9}, {%0,%1,%2,%3};"
        : "+f"(d0), "+f"(d1), "+f"(d2), "+f"(d3)
        : "r"(a0), "r"(a1), "r"(a2), "r"(a3), "r"(b0), "r"(b1));
}

// ---------------- mod = silu(vec) @ mod_w + mod_b  (3 x 6144 outputs; silu fused) ----------------
__global__ void mod_kernel(const float* __restrict__ vecp, const float* __restrict__ mod_w,
                           const float* __restrict__ mod_b, float* __restrict__ mod) {
    __shared__ float s_sv[D_MODEL];
    for (int i = threadIdx.x; i < D_MODEL; i += 256) {
        float x = vecp[i];
        s_sv[i] = x / (1.f + expf(-x));
    }
    __syncthreads();
    int o = blockIdx.x * 256 + threadIdx.x;       // 0 .. 3*6144-1
    int i = o / 6144;
    int j = o - i * 6144;
    const float* w = mod_w + (size_t)i * D_MODEL * 6144 + j;
    float acc = 0.f;
    #pragma unroll 8
    for (int d = 0; d < D_MODEL; ++d) acc = fmaf(s_sv[d], w[(size_t)d * 6144], acc);
    mod[o] = acc + mod_b[o];
}

// ---------------- LN + modulate: out = (1+sc)*ln(x) + sh ----------------
__global__ void lnmod_kernel(const float* __restrict__ x, float* __restrict__ out,
                             const float* __restrict__ sh, const float* __restrict__ sc) {
    int r = blockIdx.x;
    const float* xr = x + (size_t)r * D_MODEL;
    int t = threadIdx.x; // 256
    float v[4]; float sum = 0.f, sq = 0.f;
    #pragma unroll
    for (int i = 0; i < 4; i++) { float f = xr[t + i * 256]; v[i] = f; sum += f; sq += f * f; }
    #pragma unroll
    for (int o = 16; o; o >>= 1) {
        sum += __shfl_xor_sync(0xffffffffu, sum, o);
        sq  += __shfl_xor_sync(0xffffffffu, sq, o);
    }
    __shared__ float ssum[8], ssq[8];
    int w = t >> 5, lane = t & 31;
    if (lane == 0) { ssum[w] = sum; ssq[w] = sq; }
    __syncthreads();
    if (t == 0) {
        float S = 0.f, Q = 0.f;
        #pragma unroll
        for (int i = 0; i < 8; i++) { S += ssum[i]; Q += ssq[i]; }
        float mean = S * (1.f / D_MODEL);
        float var  = Q * (1.f / D_MODEL) - mean * mean;
        ssum[0] = mean; ssq[0] = rsqrtf(var + EPS);
    }
    __syncthreads();
    float mean = ssum[0], inv = ssq[0];
    float* orow = out + (size_t)r * D_MODEL;
    #pragma unroll
    for (int i = 0; i < 4; i++) {
        int d = t + i * 256;
        orow[d] = (1.f + sc[d]) * ((v[i] - mean) * inv) + sh[d];
    }
}

// ---------------- tf32 tensor-core GEMM, 64x128x32 tiles, fragment-packed, z-batched ----------------
#define TBM 64
#define TBN 128
#define TBK 32
#define A_OCT 516           // 4*32*4 + 4
#define A_STAGE (4 * A_OCT)
#define B_NB 66
#define B_OCT 1058          // 16*66 + 2
#define B_STAGE (4 * B_OCT)
#define GEMM_SMEM ((2 * A_STAGE + 2 * B_STAGE) * 4)   // 50368 bytes

struct BArgs {
    const float* resp[3]; // residual base pointer per z (epi 2)
    int aoff[3];      // A row offset per z
    int coff[3];      // C row offset per z
    int roff[3];      // res row offset per z (applied to resp[z])
    int m[3];         // rows per z
    long long woff[3];// weight element offset per z
    int boff[3];      // bias element offset per z
    int goff[3];      // gate element offset per z
};

__global__ void __launch_bounds__(256) gemm_tc_kernel(
        const float* __restrict__ A, const float* __restrict__ W,
        float* __restrict__ C, int N, int K,
        const float* __restrict__ bias,
        const float* __restrict__ gate,
        int epi, BArgs ba) {
    int z = blockIdx.z;
    int brow = blockIdx.y, bcol = blockIdx.x;
    if (brow * TBM >= ba.m[z]) return;

    extern __shared__ uint32_t gsm[];
    uint32_t (*As)[A_STAGE] = (uint32_t(*)[A_STAGE])gsm;
    uint32_t (*Bs)[B_STAGE] = (uint32_t(*)[B_STAGE])(gsm + 2 * A_STAGE);

    int tid  = threadIdx.x;
    int warp = tid >> 5;
    int lane = tid & 31;
    int gid  = lane >> 2;
    int tig  = lane & 3;
    int wm2  = (warp >> 2) * 2;     // mblk base (0 or 2)
    int wn8  = (warp & 3) * 4;      // nblk base

    const float* Ab = A + (size_t)ba.aoff[z] * K;
    const float* Bb = W + ba.woff[z];

    int al0 = tid, al1 = tid + 256;
    int a_row0 = al0 >> 3, a_kq0 = (al0 & 7) * 4;
    int a_row1 = al1 >> 3, a_kq1 = (al1 & 7) * 4;
    int abase0 = (a_kq0 >> 3) * A_OCT + (a_row0 >> 4) * 128 + (a_row0 & 7) * 16
               + ((a_row0 >> 3) & 1) * 2 + ((a_kq0 >> 2) & 1);
    int abase1 = (a_kq1 >> 3) * A_OCT + (a_row1 >> 4) * 128 + (a_row1 & 7) * 16
               + ((a_row1 >> 3) & 1) * 2 + ((a_kq1 >> 2) & 1);

    int b_row = tid >> 6;              // 0..3
    int b_col = (tid & 63) * 2;        // 0..126

    const float* Aptr0 = Ab + (size_t)(brow * TBM + a_row0) * K + a_kq0;
    const float* Aptr1 = Ab + (size_t)(brow * TBM + a_row1) * K + a_kq1;
    const float* Bptr  = Bb + (size_t)b_row * N + bcol * TBN + b_col;

    float acc[2][4][4];
    #pragma unroll
    for (int i = 0; i < 2; i++)
        #pragma unroll
        for (int j = 0; j < 4; j++)
            #pragma unroll
            for (int c = 0; c < 4; c++) acc[i][j][c] = 0.f;

    int iters = K / TBK;

    float4 av0 = *(const float4*)(Aptr0);
    float4 av1 = *(const float4*)(Aptr1);
    float2 bv[8];
    #pragma unroll
    for (int r = 0; r < 8; r++)
        bv[r] = *(const float2*)(Bptr + (size_t)(r * 4) * N);

    #define STORE_TILE(BUF) do {                                                     \
        As[BUF][abase0 + 0]  = __float_as_uint(av0.x);                               \
        As[BUF][abase0 + 4]  = __float_as_uint(av0.y);                               \
        As[BUF][abase0 + 8]  = __float_as_uint(av0.z);                               \
        As[BUF][abase0 + 12] = __float_as_uint(av0.w);                               \
        As[BUF][abase1 + 0]  = __float_as_uint(av1.x);                               \
        As[BUF][abase1 + 4]  = __float_as_uint(av1.y);                               \
        As[BUF][abase1 + 8]  = __float_as_uint(av1.z);                               \
        As[BUF][abase1 + 12] = __float_as_uint(av1.w);                               \
        _Pragma("unroll")                                                            \
        for (int r = 0; r < 8; r++) {                                                \
            int k   = b_row + r * 4;                                                 \
            int oct = k >> 3;                                                        \
            int j   = k & 7;                                                         \
            int jm  = j & 3;                                                         \
            int sl  = j >> 2;                                                        \
            int n7  = b_col & 7;                                                     \
            int nbl = b_col >> 3;                                                    \
            uint32_t* bb = &Bs[BUF][oct * B_OCT + nbl * B_NB + sl];                  \
            bb[(n7 * 4 + jm) * 2]       = __float_as_uint(bv[r].x);                  \
            bb[((n7 + 1) * 4 + jm) * 2] = __float_as_uint(bv[r].y);                  \
        }                                                                            \
    } while (0)

    STORE_TILE(0);
    __syncthreads();

    for (int it = 0; it < iters; ++it) {
        int cur = it & 1;
        if (it + 1 < iters) {
            int k0 = (it + 1) * TBK;
            av0 = *(const float4*)(Aptr0 + k0);
            av1 = *(const float4*)(Aptr1 + k0);
            #pragma unroll
            for (int r = 0; r < 8; r++)
                bv[r] = *(const float2*)(Bptr + (size_t)(k0 + r * 4) * N);
        }

        #pragma unroll
        for (int oct = 0; oct < 4; oct++) {
            uint4 ua[2];
            #pragma unroll
            for (int mt = 0; mt < 2; mt++)
                ua[mt] = *(const uint4*)&As[cur][oct * A_OCT + (wm2 + mt) * 128 + lane * 4];
            uint2 ub[4];
            #pragma unroll
            for (int nt = 0; nt < 4; nt++)
                ub[nt] = *(const uint2*)&Bs[cur][oct * B_OCT + (wn8 + nt) * B_NB + lane * 2];
            #pragma unroll
            for (int mt = 0; mt < 2; mt++)
                #pragma unroll
                for (int nt = 0; nt < 4; nt++)
                    mma_tf32(acc[mt][nt][0], acc[mt][nt][1], acc[mt][nt][2], acc[mt][nt][3],
                             ua[mt].x, ua[mt].z, ua[mt].y, ua[mt].w,
                             ub[nt].x, ub[nt].y);
        }

        if (it + 1 < iters) {
            int nxt = cur ^ 1;
            STORE_TILE(nxt);
            __syncthreads();
        }
    }
    #undef STORE_TILE

    // epilogue
    int wm = (warp >> 2) * 32;
    int wn = (warp & 3) * 32;
    int crow = ba.coff[z];
    int rrow = ba.roff[z];
    const float* resz = ba.resp[z];
    int bo = ba.boff[z], go = ba.goff[z];
    #pragma unroll
    for (int mt = 0; mt < 2; mt++) {
        int lrow0 = brow * TBM + wm + mt * 16 + gid;
        int lrow1 = lrow0 + 8;
        #pragma unroll
        for (int nt = 0; nt < 4; nt++) {
            int col0 = bcol * TBN + wn + nt * 8 + tig * 2;
            int col1 = col0 + 1;
            float v0 = acc[mt][nt][0], v1 = acc[mt][nt][1];
            float v2 = acc[mt][nt][2], v3 = acc[mt][nt][3];
            if (epi == 1) {
                v0 = gelu_tanh(v0 + bias[bo + col0]); v1 = gelu_tanh(v1 + bias[bo + col1]);
                v2 = gelu_tanh(v2 + bias[bo + col0]); v3 = gelu_tanh(v3 + bias[bo + col1]);
            } else if (epi == 2) {
                v0 = resz[(size_t)(rrow + lrow0) * N + col0] + gate[go + col0] * (v0 + bias[bo + col0]);
                v1 = resz[(size_t)(rrow + lrow0) * N + col1] + gate[go + col1] * (v1 + bias[bo + col1]);
                v2 = resz[(size_t)(rrow + lrow1) * N + col0] + gate[go + col0] * (v2 + bias[bo + col0]);
                v3 = resz[(size_t)(rrow + lrow1) * N + col1] + gate[go + col1] * (v3 + bias[bo + col1]);
            }
            C[(size_t)(crow + lrow0) * N + col0] = v0;
            C[(size_t)(crow + lrow0) * N + col1] = v1;
            C[(size_t)(crow + lrow1) * N + col0] = v2;
            C[(size_t)(crow + lrow1) * N + col1] = v3;
        }
    }
}

// ---------------- QKV post: RMS + scale + RoPE + tf32 pre-round + scatter ----------------
__global__ void qkvpost_kernel(const float* __restrict__ Y, const float* __restrict__ pe,
                               const float* __restrict__ q_scale, const float* __restrict__ k_scale,
                               float* __restrict__ Q, float* __restrict__ K, float* __restrict__ V) {
    int gw = blockIdx.x * 8 + (threadIdx.x >> 5);   // warp id: 0 .. 2304*16-1
    int lane = threadIdx.x & 31;
    int l = gw >> 4;
    int h = gw & 15;
    int i = (l < L_TXT) ? 2 : (l < (L_TXT + L_IMG) ? 0 : 1);
    bool is_tmp = (l >= L_TXT + L_IMG);

    const float* row = Y + (size_t)l * 3072 + h * HD;
    float q0 = row[2 * lane],        q1 = row[2 * lane + 1];
    float k0 = row[1024 + 2 * lane], k1 = row[1024 + 2 * lane + 1];
    float v0 = row[2048 + 2 * lane], v1 = row[2048 + 2 * lane + 1];

    float qs = q0 * q0 + q1 * q1;
    float ks = k0 * k0 + k1 * k1;
    #pragma unroll
    for (int o = 16; o; o >>= 1) {
        qs += __shfl_xor_sync(0xffffffffu, qs, o);
        ks += __shfl_xor_sync(0xffffffffu, ks, o);
    }
    float qinv = rsqrtf(qs * (1.f / HD) + EPS);
    float kinv = rsqrtf(ks * (1.f / HD) + EPS);

    float qn0 = q0 * qinv * q_scale[i * HD + 2 * lane];
    float qn1 = q1 * qinv * q_scale[i * HD + 2 * lane + 1];
    float kn0 = k0 * kinv * k_scale[i * HD + 2 * lane];
    float kn1 = k1 * kinv * k_scale[i * HD + 2 * lane + 1];

    const float* p = pe + ((size_t)l * 32 + lane) * 4;
    float p00 = p[0], p01 = p[1], p10 = p[2], p11 = p[3];

    size_t base = ((size_t)h * L_ALL + l) * HD + 2 * lane;
    Q[base]     = __uint_as_float(f2tf32((p00 * qn0 + p01 * qn1) * ATTN_SCALE));
    Q[base + 1] = __uint_as_float(f2tf32((p10 * qn0 + p11 * qn1) * ATTN_SCALE));
    K[base]     = __uint_as_float(f2tf32(p00 * kn0 + p01 * kn1));
    K[base + 1] = __uint_as_float(f2tf32(p10 * kn0 + p11 * kn1));
    if (is_tmp) {
        V[base]     = __uint_as_float(f2tf32(qn0));
        V[base + 1] = __uint_as_float(f2tf32(qn1));
    } else {
        V[base]     = __uint_as_float(f2tf32(v0));
        V[base + 1] = __uint_as_float(f2tf32(v1));
    }
}

// ---------------- flash attention on tensor cores (tf32 mma, inputs pre-rounded) ----------------
// 128 q-rows per block, 8 warps x 16 rows; 64-key tiles.
#define ATQ 128
#define ATK 64
#define ALD 68
#define ATTN_SMEM ((2 * ATK * ALD + ATQ * ALD) * 4)   // 69632 bytes

__global__ void __launch_bounds__(256) attn_tc_kernel(
        const float* __restrict__ Q, const float* __restrict__ K,
        const float* __restrict__ V, float* __restrict__ Aout) {
    extern __shared__ uint32_t dyn[];
    uint32_t (*Ks)[ALD] = (uint32_t(*)[ALD])dyn;
    uint32_t (*Vs)[ALD] = (uint32_t(*)[ALD])(dyn + ATK * ALD);
    uint32_t (*Ps)[ALD] = (uint32_t(*)[ALD])(dyn + 2 * ATK * ALD);   // 128 rows

    int h   = blockIdx.y;
    int q0  = blockIdx.x * ATQ;
    int tid = threadIdx.x;          // 256
    int warp = tid >> 5;            // 0..7 -> q rows [warp*16, warp*16+16)
    int lane = tid & 31;
    int gid  = lane >> 2;
    int tig  = lane & 3;
    int w16  = warp * 16;

    const uint32_t* Qh = (const uint32_t*)(Q + (size_t)h * L_ALL * HD);
    const uint32_t* Kh = (const uint32_t*)(K + (size_t)h * L_ALL * HD);
    const uint32_t* Vh = (const uint32_t*)(V + (size_t)h * L_ALL * HD);

    // stage Q: 128 rows x 16 float4 = 2048 uint4, 8 per thread
    #pragma unroll
    for (int i = 0; i < 8; i++) {
        int linear = tid + i * 256;
        int r = linear >> 4;
        int c4 = (linear & 15) * 4;
        uint4 qv = *(const uint4*)(Qh + (size_t)(q0 + r) * HD + c4);
        *(uint4*)&Ps[r][c4] = qv;
    }
    __syncthreads();

    uint32_t qf[8][4];
    #pragma unroll
    for (int ks = 0; ks < 8; ks++) {
        qf[ks][0] = Ps[w16 + gid][ks * 8 + tig];
        qf[ks][1] = Ps[w16 + gid + 8][ks * 8 + tig];
        qf[ks][2] = Ps[w16 + gid][ks * 8 + tig + 4];
        qf[ks][3] = Ps[w16 + gid + 8][ks * 8 + tig + 4];
    }

    float oacc[8][4];
    #pragma unroll
    for (int nt = 0; nt < 8; nt++)
        #pragma unroll
        for (int c = 0; c < 4; c++) oacc[nt][c] = 0.f;
    float m0 = -INFINITY, m1 = -INFINITY, l0 = 0.f, l1 = 0.f;

    for (int kb = 0; kb < L_ALL; kb += ATK) {
        __syncthreads();
        // load K/V tile: 64 rows x 16 float4 x2 = 2048 uint4, 4 per thread each
        #pragma unroll
        for (int i = 0; i < 4; i++) {
            int linear = tid + i * 256;
            int r = linear >> 4;
            int c4 = (linear & 15) * 4;
            uint4 kv = *(const uint4*)(Kh + (size_t)(kb + r) * HD + c4);
            uint4 vv = *(const uint4*)(Vh + (size_t)(kb + r) * HD + c4);
            *(uint4*)&Ks[r][c4] = kv;
            *(uint4*)&Vs[r][c4] = vv;
        }
        __syncthreads();

        float sacc[8][4];
        #pragma unroll
        for (int nt = 0; nt < 8; nt++)
            #pragma unroll
            for (int c = 0; c < 4; c++) sacc[nt][c] = 0.f;
        #pragma unroll
        for (int ks = 0; ks < 8; ks++) {
            #pragma unroll
            for (int nt = 0; nt < 8; nt++) {
                uint32_t b0 = Ks[nt * 8 + gid][ks * 8 + tig];
                uint32_t b1 = Ks[nt * 8 + gid][ks * 8 + tig + 4];
                mma_tf32(sacc[nt][0], sacc[nt][1], sacc[nt][2], sacc[nt][3],
                         qf[ks][0], qf[ks][1], qf[ks][2], qf[ks][3], b0, b1);
            }
        }

        float t0 = -INFINITY, t1 = -INFINITY;
        #pragma unroll
        for (int nt = 0; nt < 8; nt++) {
            t0 = fmaxf(t0, fmaxf(sacc[nt][0], sacc[nt][1]));
            t1 = fmaxf(t1, fmaxf(sacc[nt][2], sacc[nt][3]));
        }
        t0 = fmaxf(t0, __shfl_xor_sync(0xffffffffu, t0, 1));
        t0 = fmaxf(t0, __shfl_xor_sync(0xffffffffu, t0, 2));
        t1 = fmaxf(t1, __shfl_xor_sync(0xffffffffu, t1, 1));
        t1 = fmaxf(t1, __shfl_xor_sync(0xffffffffu, t1, 2));
        float mn0 = fmaxf(m0, t0), mn1 = fmaxf(m1, t1);
        float al0 = __expf(m0 - mn0), al1 = __expf(m1 - mn1);
        m0 = mn0; m1 = mn1;

        float ts0 = 0.f, ts1 = 0.f;
        #pragma unroll
        for (int nt = 0; nt < 8; nt++) {
            int c0 = nt * 8 + tig * 2;
            uint32_t p00 = f2tf32(__expf(sacc[nt][0] - mn0));
            uint32_t p01 = f2tf32(__expf(sacc[nt][1] - mn0));
            uint32_t p10 = f2tf32(__expf(sacc[nt][2] - mn1));
            uint32_t p11 = f2tf32(__expf(sacc[nt][3] - mn1));
            Ps[w16 + gid][c0]         = p00;
            Ps[w16 + gid][c0 + 1]     = p01;
            Ps[w16 + gid + 8][c0]     = p10;
            Ps[w16 + gid + 8][c0 + 1] = p11;
            ts0 += __uint_as_float(p00) + __uint_as_float(p01);
            ts1 += __uint_as_float(p10) + __uint_as_float(p11);
        }
        ts0 += __shfl_xor_sync(0xffffffffu, ts0, 1);
        ts0 += __shfl_xor_sync(0xffffffffu, ts0, 2);
        ts1 += __shfl_xor_sync(0xffffffffu, ts1, 1);
        ts1 += __shfl_xor_sync(0xffffffffu, ts1, 2);
        l0 = l0 * al0 + ts0;
        l1 = l1 * al1 + ts1;

        #pragma unroll
        for (int nt = 0; nt < 8; nt++) {
            oacc[nt][0] *= al0; oacc[nt][1] *= al0;
            oacc[nt][2] *= al1; oacc[nt][3] *= al1;
        }
        __syncwarp();

        #pragma unroll
        for (int ks = 0; ks < 8; ks++) {
            uint32_t a0 = Ps[w16 + gid][ks * 8 + tig];
            uint32_t a1 = Ps[w16 + gid + 8][ks * 8 + tig];
            uint32_t a2 = Ps[w16 + gid][ks * 8 + tig + 4];
            uint32_t a3 = Ps[w16 + gid + 8][ks * 8 + tig + 4];
            #pragma unroll
            for (int nt = 0; nt < 8; nt++) {
                uint32_t b0 = Vs[ks * 8 + tig][nt * 8 + gid];
                uint32_t b1 = Vs[ks * 8 + tig + 4][nt * 8 + gid];
                mma_tf32(oacc[nt][0], oacc[nt][1], oacc[nt][2], oacc[nt][3],
                         a0, a1, a2, a3, b0, b1);
            }
        }
        __syncwarp();
    }

    float i0 = 1.f / l0, i1 = 1.f / l1;
    int r0 = q0 + w16 + gid;
    int r1 = r0 + 8;
    #pragma unroll
    for (int nt = 0; nt < 8; nt++) {
        int c0 = h * HD + nt * 8 + tig * 2;
        Aout[(size_t)r0 * D_MODEL + c0]     = oacc[nt][0] * i0;
        Aout[(size_t)r0 * D_MODEL + c0 + 1] = oacc[nt][1] * i0;
        Aout[(size_t)r1 * D_MODEL + c0]     = oacc[nt][2] * i1;
        Aout[(size_t)r1 * D_MODEL + c0 + 1] = oacc[nt][3] * i1;
    }
}

extern "C" void kernel_launch(void* const* d_in, const int* in_sizes, int n_in,
                              void* d_out, int out_size) {
    const float* img      = (const float*)d_in[0];
    const float* temporal = (const float*)d_in[1];
    const float* txt      = (const float*)d_in[2];
    const float* vec      = (const float*)d_in[3];
    const float* pe       = (const float*)d_in[4];
    const float* mod_w    = (const float*)d_in[5];
    const float* mod_b    = (const float*)d_in[6];
    const float* qkv_w    = (const float*)d_in[7];
    const float* q_scale  = (const float*)d_in[8];
    const float* k_scale  = (const float*)d_in[9];
    const float* proj_w   = (const float*)d_in[10];
    const float* proj_b   = (const float*)d_in[11];
    const float* mlp_w1   = (const float*)d_in[12];
    const float* mlp_b1   = (const float*)d_in[13];
    const float* mlp_w2   = (const float*)d_in[14];
    const float* mlp_b2   = (const float*)d_in[15];
    float* out = (float*)d_out;

    static float *mod = 0, *xm = 0, *qkv = 0, *Qb = 0, *Kb = 0, *Vb = 0,
                 *attn = 0, *x1 = 0, *ym = 0, *hbuf = 0;
    if (!mod) {
        cudaGetSymbolAddress((void**)&mod,  g_mod);
        cudaGetSymbolAddress((void**)&xm,   g_xm);
        cudaGetSymbolAddress((void**)&qkv,  g_qkv);
        cudaGetSymbolAddress((void**)&Qb,   g_Q);
        cudaGetSymbolAddress((void**)&Kb,   g_K);
        cudaGetSymbolAddress((void**)&Vb,   g_V);
        cudaGetSymbolAddress((void**)&attn, g_attn);
        cudaGetSymbolAddress((void**)&x1,   g_x1);
        cudaGetSymbolAddress((void**)&ym,   g_ym);
        cudaGetSymbolAddress((void**)&hbuf, g_h);
        cudaFuncSetAttribute(attn_tc_kernel,
                             cudaFuncAttributeMaxDynamicSharedMemorySize, ATTN_SMEM);
        cudaFuncSetAttribute(gemm_tc_kernel,
                             cudaFuncAttributeMaxDynamicSharedMemorySize, GEMM_SMEM);
    }

    const int off_txt = 0;
    const int off_img = L_TXT;
    const int off_tmp = L_TXT + L_IMG;

    // 1. mod (silu fused)
    mod_kernel<<<(3 * 6144) / 256, 256>>>(vec, mod_w, mod_b, mod);

    // 2. LN1 + modulate
    lnmod_kernel<<<L_TXT, 256>>>(txt,      xm + (size_t)off_txt * D_MODEL, mod + 2 * 6144, mod + 2 * 6144 + 1024);
    lnmod_kernel<<<L_IMG, 256>>>(img,      xm + (size_t)off_img * D_MODEL, mod + 0,        mod + 1024);
    lnmod_kernel<<<L_TMP, 256>>>(temporal, xm + (size_t)off_tmp * D_MODEL, mod + 1 * 6144, mod + 1 * 6144 + 1024);

    // 3. QKV (batched z=3: txt->w2, img->w0, tmp->w1)
    {
        BArgs ba = {};
        int ao[3] = {off_txt, off_img, off_tmp};
        for (int z = 0; z < 3; z++) { ba.aoff[z] = ao[z]; ba.coff[z] = ao[z]; }
        ba.m[0] = 256; ba.m[1] = 1024; ba.m[2] = 1024;
        ba.woff[0] = 2LL * 1024 * 3072; ba.woff[1] = 0; ba.woff[2] = 1LL * 1024 * 3072;
        gemm_tc_kernel<<<dim3(3072 / TBN, 16, 3), 256, GEMM_SMEM>>>(xm, qkv_w, qkv, 3072, 1024,
                                                                    proj_b, mod, 0, ba);
    }

    // 4. RMS + scale + RoPE + tf32 pre-round + scatter
    qkvpost_kernel<<<(L_ALL * NH) / 8, 256>>>(qkv, pe, q_scale, k_scale, Qb, Kb, Vb);

    // 5. attention (128 q-rows per block)
    attn_tc_kernel<<<dim3(L_ALL / ATQ, NH), 256, ATTN_SMEM>>>(Qb, Kb, Vb, attn);

    // 6. proj + gate + residual (batched z=3; residuals read original inputs directly)
    {
        BArgs ba = {};
        int ao[3] = {off_txt, off_img, off_tmp};
        int wi[3] = {2, 0, 1};
        const float* rp[3] = {txt, img, temporal};
        for (int z = 0; z < 3; z++) {
            ba.aoff[z] = ao[z]; ba.coff[z] = ao[z]; ba.roff[z] = 0;
            ba.resp[z] = rp[z];
            ba.woff[z] = (long long)wi[z] * 1024 * 1024;
            ba.boff[z] = wi[z] * 1024;
            ba.goff[z] = wi[z] * 6144 + 2048;
        }
        ba.m[0] = 256; ba.m[1] = 1024; ba.m[2] = 1024;
        gemm_tc_kernel<<<dim3(1024 / TBN, 16, 3), 256, GEMM_SMEM>>>(attn, proj_w, x1, 1024, 1024,
                                                                    proj_b, mod, 2, ba);
    }

    // 7. img + txt MLP (batched z=2); temporal must wait for final img
    lnmod_kernel<<<L_IMG, 256>>>(x1 + (size_t)off_img * D_MODEL, ym,
                                 mod + 0 * 6144 + 3072, mod + 0 * 6144 + 4096);
    lnmod_kernel<<<L_TXT, 256>>>(x1 + (size_t)off_txt * D_MODEL, ym + (size_t)1024 * D_MODEL,
                                 mod + 2 * 6144 + 3072, mod + 2 * 6144 + 4096);
    {
        BArgs ba = {};
        ba.aoff[0] = 0;    ba.coff[0] = 0;    ba.m[0] = 1024;
        ba.woff[0] = 0;    ba.boff[0] = 0;
        ba.aoff[1] = 1024; ba.coff[1] = 1024; ba.m[1] = 256;
        ba.woff[1] = 2LL * 1024 * 4096; ba.boff[1] = 2 * 4096;
        gemm_tc_kernel<<<dim3(4096 / TBN, 16, 2), 256, GEMM_SMEM>>>(ym, mlp_w1, hbuf, 4096, 1024,
                                                                    mlp_b1, mod, 1, ba);
    }
    {
        BArgs ba = {};
        ba.aoff[0] = 0;    ba.coff[0] = 0;    ba.roff[0] = off_img; ba.resp[0] = x1; ba.m[0] = 1024;
        ba.woff[0] = 0;    ba.boff[0] = 0;    ba.goff[0] = 0 * 6144 + 5120;
        ba.aoff[1] = 1024; ba.coff[1] = 2048; ba.roff[1] = off_txt; ba.resp[1] = x1; ba.m[1] = 256;
        ba.woff[1] = 2LL * 4096 * 1024; ba.boff[1] = 2 * 1024; ba.goff[1] = 2 * 6144 + 5120;
        gemm_tc_kernel<<<dim3(1024 / TBN, 16, 2), 256, GEMM_SMEM>>>(hbuf, mlp_w2, out, 1024, 4096,
                                                                    mlp_b2, mod, 2, ba);
    }

    // 8. temporal MLP: LN of FINAL img (reference quirk), residual = x1 tmp rows
    lnmod_kernel<<<L_TMP, 256>>>(out, ym, mod + 1 * 6144 + 3072, mod + 1 * 6144 + 4096);
    {
        BArgs ba = {};
        ba.aoff[0] = 0; ba.coff[0] = 0; ba.m[0] = 1024;
        ba.woff[0] = 1LL * 1024 * 4096; ba.boff[0] = 4096;
        gemm_tc_kernel<<<dim3(4096 / TBN, 16, 1), 256, GEMM_SMEM>>>(ym, mlp_w1, hbuf, 4096, 1024,
                                                                    mlp_b1, mod, 1, ba);
    }
    {
        BArgs ba = {};
        ba.aoff[0] = 0; ba.coff[0] = 1024; ba.roff[0] = off_tmp; ba.resp[0] = x1; ba.m[0] = 1024;
        ba.woff[0] = 1LL * 4096 * 1024; ba.boff[0] = 1024; ba.goff[0] = 1 * 6144 + 5120;
        gemm_tc_kernel<<<dim3(1024 / TBN, 16, 1), 256, GEMM_SMEM>>>(hbuf, mlp_w2, out, 1024, 4096,
                                                                    mlp_b2, mod, 2, ba);
    }
}

// round 15
// speedup vs baseline: 1.1637x; 1.1637x over previous
#include <cuda_runtime.h>
#include <cuda_bf16.h>
#include <cuda_fp16.h>
#include <math.h>
#include <stdint.h>

// ---------------- problem constants ----------------
#define L_TXT 256
#define L_IMG 1024
#define L_TMP 1024
#define L_ALL 2304          // txt + img + tmp
#define D_MODEL 1024
#define NH 16
#define HD 64
#define D_MLP 4096
#define EPS 1e-6f
#define ATTN_SCALE 0.125f   // 1/sqrt(64)

// ---------------- scratch (static device memory; no allocation) ----------------
__device__ float g_mod[3 * 6144];
__device__ float g_xm[L_ALL * D_MODEL];        // LN1-modulated, concat order [txt|img|tmp]
__device__ float g_qkv[L_ALL * 3 * D_MODEL];   // QKV gemm out, same row order
__device__ float g_Q[NH * L_ALL * HD];         // tf32-rounded, pre-scaled by ATTN_SCALE
__device__ float g_K[NH * L_ALL * HD];         // tf32-rounded
__device__ float g_V[NH * L_ALL * HD];         // tf32-rounded
__device__ float g_attn[L_ALL * D_MODEL];      // [l][h*64+d], concat order
__device__ float g_x1[L_ALL * D_MODEL];        // post-proj residual, concat order
__device__ float g_ym[1280 * D_MODEL];         // LN2-modulated (img rows 0..1023, txt rows 1024..1279)
__device__ float g_h[1280 * D_MLP];            // MLP hidden

// ---------------- helpers ----------------
__device__ __forceinline__ float gelu_tanh(float x) {
    const float c = 0.7978845608028654f; // sqrt(2/pi)
    float x3 = x * x * x;
    return 0.5f * x * (1.f + tanhf(c * (x + 0.044715f * x3)));
}

__device__ __forceinline__ uint32_t f2tf32(float f) {
    uint32_t u;
    asm("cvt.rna.tf32.f32 %0, %1;" : "=r"(u) : "f"(f));
    return u;
}

__device__ __forceinline__ uint32_t pack_h2(float a, float b) {
    __half2 h = __floats2half2_rn(a, b);
    return *(uint32_t*)&h;
}

__device__ __forceinline__ void mma_tf32(float& d0, float& d1, float& d2, float& d3,
                                         uint32_t a0, uint32_t a1, uint32_t a2, uint32_t a3,
                                         uint32_t b0, uint32_t b1) {
    asm volatile(
        "mma.sync.aligned.m16n8k8.row.col.f32.tf32.tf32.f32 "
        "{%0,%1,%2,%3}, {%4,%5,%6,%7}, {%8,%9}, {%0,%1,%2,%3};"
        : "+f"(d0), "+f"(d1), "+f"(d2), "+f"(d3)
        : "r"(a0), "r"(a1), "r"(a2), "r"(a3), "r"(b0), "r"(b1));
}

__device__ __forceinline__ void mma_f16(float& d0, float& d1, float& d2, float& d3,
                                        uint32_t a0, uint32_t a1, uint32_t a2, uint32_t a3,
                                        uint32_t b0, uint32_t b1) {
    asm volatile(
        "mma.sync.aligned.m16n8k16.row.col.f32.f16.f16.f32 "
        "{%0,%1,%2,%3}, {%4,%5,%6,%7}, {%8,%9}, {%0,%1,%2,%3};"
        : "+f"(d0), "+f"(d1), "+f"(d2), "+f"(d3)
        : "r"(a0), "r"(a1), "r"(a2), "r"(a3), "r"(b0), "r"(b1));
}

// ---------------- mod = silu(vec) @ mod_w + mod_b  (silu fused) ----------------
__global__ void mod_kernel(const float* __restrict__ vecp, const float* __restrict__ mod_w,
                           const float* __restrict__ mod_b, float* __restrict__ mod) {
    __shared__ float s_sv[D_MODEL];
    for (int i = threadIdx.x; i < D_MODEL; i += 256) {
        float x = vecp[i];
        s_sv[i] = x / (1.f + expf(-x));
    }
    __syncthreads();
    int o = blockIdx.x * 256 + threadIdx.x;       // 0 .. 3*6144-1
    int i = o / 6144;
    int j = o - i * 6144;
    const float* w = mod_w + (size_t)i * D_MODEL * 6144 + j;
    float acc = 0.f;
    #pragma unroll 8
    for (int d = 0; d < D_MODEL; ++d) acc = fmaf(s_sv[d], w[(size_t)d * 6144], acc);
    mod[o] = acc + mod_b[o];
}

// ---------------- LN + modulate: out = (1+sc)*ln(x) + sh ----------------
__global__ void lnmod_kernel(const float* __restrict__ x, float* __restrict__ out,
                             const float* __restrict__ sh, const float* __restrict__ sc) {
    int r = blockIdx.x;
    const float* xr = x + (size_t)r * D_MODEL;
    int t = threadIdx.x; // 256
    float v[4]; float sum = 0.f, sq = 0.f;
    #pragma unroll
    for (int i = 0; i < 4; i++) { float f = xr[t + i * 256]; v[i] = f; sum += f; sq += f * f; }
    #pragma unroll
    for (int o = 16; o; o >>= 1) {
        sum += __shfl_xor_sync(0xffffffffu, sum, o);
        sq  += __shfl_xor_sync(0xffffffffu, sq, o);
    }
    __shared__ float ssum[8], ssq[8];
    int w = t >> 5, lane = t & 31;
    if (lane == 0) { ssum[w] = sum; ssq[w] = sq; }
    __syncthreads();
    if (t == 0) {
        float S = 0.f, Q = 0.f;
        #pragma unroll
        for (int i = 0; i < 8; i++) { S += ssum[i]; Q += ssq[i]; }
        float mean = S * (1.f / D_MODEL);
        float var  = Q * (1.f / D_MODEL) - mean * mean;
        ssum[0] = mean; ssq[0] = rsqrtf(var + EPS);
    }
    __syncthreads();
    float mean = ssum[0], inv = ssq[0];
    float* orow = out + (size_t)r * D_MODEL;
    #pragma unroll
    for (int i = 0; i < 4; i++) {
        int d = t + i * 256;
        orow[d] = (1.f + sc[d]) * ((v[i] - mean) * inv) + sh[d];
    }
}

// ---------------- fp16 tensor-core GEMM, 64x128x32 tiles, fragment-packed (half2 words) ----------------
// Same proven word layout as the tf32 version, with each 32-bit word = half2 of
// two consecutive k elements; k-blocks are 16 wide ("hex") instead of 8.
#define TBM 64
#define TBN 128
#define TBK 32
#define A_HEX 516           // 4 mblk * 128 words + 4 pad
#define A_STAGE (2 * A_HEX)
#define B_NB 66
#define B_HEX 1058          // 16*66 + 2
#define B_STAGE (2 * B_HEX)
#define GEMM_SMEM ((2 * A_STAGE + 2 * B_STAGE) * 4)   // 25184 bytes

struct BArgs {
    const float* resp[3]; // residual base pointer per z (epi 2)
    int aoff[3];      // A row offset per z
    int coff[3];      // C row offset per z
    int roff[3];      // res row offset per z (applied to resp[z])
    int m[3];         // rows per z
    long long woff[3];// weight element offset per z
    int boff[3];      // bias element offset per z
    int goff[3];      // gate element offset per z
};

__global__ void __launch_bounds__(256) gemm_tc_kernel(
        const float* __restrict__ A, const float* __restrict__ W,
        float* __restrict__ C, int N, int K,
        const float* __restrict__ bias,
        const float* __restrict__ gate,
        int epi, BArgs ba) {
    int z = blockIdx.z;
    int brow = blockIdx.y, bcol = blockIdx.x;
    if (brow * TBM >= ba.m[z]) return;

    extern __shared__ uint32_t gsm[];
    uint32_t (*As)[A_STAGE] = (uint32_t(*)[A_STAGE])gsm;
    uint32_t (*Bs)[B_STAGE] = (uint32_t(*)[B_STAGE])(gsm + 2 * A_STAGE);

    int tid  = threadIdx.x;
    int warp = tid >> 5;
    int lane = tid & 31;
    int gid  = lane >> 2;
    int tig  = lane & 3;
    int wm2  = (warp >> 2) * 2;     // mblk base (0 or 2)
    int wn8  = (warp & 3) * 4;      // nblk base

    const float* Ab = A + (size_t)ba.aoff[z] * K;
    const float* Bb = W + ba.woff[z];

    // A tile 64x32 = 512 float4 -> 2 per thread
    int al0 = tid, al1 = tid + 256;
    int a_row0 = al0 >> 3, a_kq0 = (al0 & 7) * 4;   // k multiple of 4
    int a_row1 = al1 >> 3, a_kq1 = (al1 & 7) * 4;
    // half2 pair index kp = k/2; word offset formula identical to tf32 with k->kp
    int kp0a = (a_kq0 >> 1) & 7, hex0a = a_kq0 >> 4;
    int kp1a = (a_kq1 >> 1) & 7, hex1a = a_kq1 >> 4;
    int abase0 = hex0a * A_HEX + (a_row0 >> 4) * 128 + (a_row0 & 7) * 16
               + ((a_row0 >> 3) & 1) * 2 + ((kp0a >> 2) & 1) + (kp0a & 3) * 4;
    int abase1 = hex1a * A_HEX + (a_row1 >> 4) * 128 + (a_row1 & 7) * 16
               + ((a_row1 >> 3) & 1) * 2 + ((kp1a >> 2) & 1) + (kp1a & 3) * 4;

    // B tile 32x128 = 2048 float2 -> 8 per thread; k rows b_row + r*4, r=0..7
    int b_row = tid >> 6;              // 0..3
    int b_col = (tid & 63) * 2;        // 0..126 (even)
    int n7  = b_col & 7;
    int nbl = b_col >> 3;

    const float* Aptr0 = Ab + (size_t)(brow * TBM + a_row0) * K + a_kq0;
    const float* Aptr1 = Ab + (size_t)(brow * TBM + a_row1) * K + a_kq1;
    const float* Bptr  = Bb + (size_t)b_row * N + bcol * TBN + b_col;

    float acc[2][4][4];
    #pragma unroll
    for (int i = 0; i < 2; i++)
        #pragma unroll
        for (int j = 0; j < 4; j++)
            #pragma unroll
            for (int c = 0; c < 4; c++) acc[i][j][c] = 0.f;

    int iters = K / TBK;

    float4 av0 = *(const float4*)(Aptr0);
    float4 av1 = *(const float4*)(Aptr1);
    float2 bv[8];
    #pragma unroll
    for (int r = 0; r < 8; r++)
        bv[r] = *(const float2*)(Bptr + (size_t)(r * 4) * N);

    // store tile: convert to half2 words
    #define STORE_TILE(BUF) do {                                                     \
        As[BUF][abase0]     = pack_h2(av0.x, av0.y);                                 \
        As[BUF][abase0 + 4] = pack_h2(av0.z, av0.w);                                 \
        As[BUF][abase1]     = pack_h2(av1.x, av1.y);                                 \
        As[BUF][abase1 + 4] = pack_h2(av1.z, av1.w);                                 \
        _Pragma("unroll")                                                            \
        for (int r = 0; r < 8; r++) {                                                \
            int k   = b_row + r * 4;                                                 \
            int hex = k >> 4;                                                        \
            int kp  = (k >> 1) & 7;                                                  \
            int sl  = (kp >> 2) & 1;                                                 \
            int jm  = kp & 3;                                                        \
            int par = k & 1;                                                         \
            uint32_t* bb = &Bs[BUF][hex * B_HEX + nbl * B_NB + sl];                  \
            ((__half*)&bb[(n7 * 4 + jm) * 2])[par]       = __float2half_rn(bv[r].x);\
            ((__half*)&bb[((n7 + 1) * 4 + jm) * 2])[par] = __float2half_rn(bv[r].y);\
        }                                                                            \
    } while (0)

    STORE_TILE(0);
    __syncthreads();

    for (int it = 0; it < iters; ++it) {
        int cur = it & 1;
        if (it + 1 < iters) {
            int k0 = (it + 1) * TBK;
            av0 = *(const float4*)(Aptr0 + k0);
            av1 = *(const float4*)(Aptr1 + k0);
            #pragma unroll
            for (int r = 0; r < 8; r++)
                bv[r] = *(const float2*)(Bptr + (size_t)(k0 + r * 4) * N);
        }

        #pragma unroll
        for (int hex = 0; hex < 2; hex++) {
            uint4 ua[2];
            #pragma unroll
            for (int mt = 0; mt < 2; mt++)
                ua[mt] = *(const uint4*)&As[cur][hex * A_HEX + (wm2 + mt) * 128 + lane * 4];
            uint2 ub[4];
            #pragma unroll
            for (int nt = 0; nt < 4; nt++)
                ub[nt] = *(const uint2*)&Bs[cur][hex * B_HEX + (wn8 + nt) * B_NB + lane * 2];
            #pragma unroll
            for (int mt = 0; mt < 2; mt++)
                #pragma unroll
                for (int nt = 0; nt < 4; nt++)
                    mma_f16(acc[mt][nt][0], acc[mt][nt][1], acc[mt][nt][2], acc[mt][nt][3],
                            ua[mt].x, ua[mt].z, ua[mt].y, ua[mt].w,
                            ub[nt].x, ub[nt].y);
        }

        if (it + 1 < iters) {
            int nxt = cur ^ 1;
            STORE_TILE(nxt);
            __syncthreads();
        }
    }
    #undef STORE_TILE

    // epilogue
    int wm = (warp >> 2) * 32;
    int wn = (warp & 3) * 32;
    int crow = ba.coff[z];
    int rrow = ba.roff[z];
    const float* resz = ba.resp[z];
    int bo = ba.boff[z], go = ba.goff[z];
    #pragma unroll
    for (int mt = 0; mt < 2; mt++) {
        int lrow0 = brow * TBM + wm + mt * 16 + gid;
        int lrow1 = lrow0 + 8;
        #pragma unroll
        for (int nt = 0; nt < 4; nt++) {
            int col0 = bcol * TBN + wn + nt * 8 + tig * 2;
            int col1 = col0 + 1;
            float v0 = acc[mt][nt][0], v1 = acc[mt][nt][1];
            float v2 = acc[mt][nt][2], v3 = acc[mt][nt][3];
            if (epi == 1) {
                v0 = gelu_tanh(v0 + bias[bo + col0]); v1 = gelu_tanh(v1 + bias[bo + col1]);
                v2 = gelu_tanh(v2 + bias[bo + col0]); v3 = gelu_tanh(v3 + bias[bo + col1]);
            } else if (epi == 2) {
                v0 = resz[(size_t)(rrow + lrow0) * N + col0] + gate[go + col0] * (v0 + bias[bo + col0]);
                v1 = resz[(size_t)(rrow + lrow0) * N + col1] + gate[go + col1] * (v1 + bias[bo + col1]);
                v2 = resz[(size_t)(rrow + lrow1) * N + col0] + gate[go + col0] * (v2 + bias[bo + col0]);
                v3 = resz[(size_t)(rrow + lrow1) * N + col1] + gate[go + col1] * (v3 + bias[bo + col1]);
            }
            C[(size_t)(crow + lrow0) * N + col0] = v0;
            C[(size_t)(crow + lrow0) * N + col1] = v1;
            C[(size_t)(crow + lrow1) * N + col0] = v2;
            C[(size_t)(crow + lrow1) * N + col1] = v3;
        }
    }
}

// ---------------- QKV post: RMS + scale + RoPE + tf32 pre-round + scatter ----------------
__global__ void qkvpost_kernel(const float* __restrict__ Y, const float* __restrict__ pe,
                               const float* __restrict__ q_scale, const float* __restrict__ k_scale,
                               float* __restrict__ Q, float* __restrict__ K, float* __restrict__ V) {
    int gw = blockIdx.x * 8 + (threadIdx.x >> 5);   // warp id: 0 .. 2304*16-1
    int lane = threadIdx.x & 31;
    int l = gw >> 4;
    int h = gw & 15;
    int i = (l < L_TXT) ? 2 : (l < (L_TXT + L_IMG) ? 0 : 1);
    bool is_tmp = (l >= L_TXT + L_IMG);

    const float* row = Y + (size_t)l * 3072 + h * HD;
    float q0 = row[2 * lane],        q1 = row[2 * lane + 1];
    float k0 = row[1024 + 2 * lane], k1 = row[1024 + 2 * lane + 1];
    float v0 = row[2048 + 2 * lane], v1 = row[2048 + 2 * lane + 1];

    float qs = q0 * q0 + q1 * q1;
    float ks = k0 * k0 + k1 * k1;
    #pragma unroll
    for (int o = 16; o; o >>= 1) {
        qs += __shfl_xor_sync(0xffffffffu, qs, o);
        ks += __shfl_xor_sync(0xffffffffu, ks, o);
    }
    float qinv = rsqrtf(qs * (1.f / HD) + EPS);
    float kinv = rsqrtf(ks * (1.f / HD) + EPS);

    float qn0 = q0 * qinv * q_scale[i * HD + 2 * lane];
    float qn1 = q1 * qinv * q_scale[i * HD + 2 * lane + 1];
    float kn0 = k0 * kinv * k_scale[i * HD + 2 * lane];
    float kn1 = k1 * kinv * k_scale[i * HD + 2 * lane + 1];

    const float* p = pe + ((size_t)l * 32 + lane) * 4;
    float p00 = p[0], p01 = p[1], p10 = p[2], p11 = p[3];

    size_t base = ((size_t)h * L_ALL + l) * HD + 2 * lane;
    Q[base]     = __uint_as_float(f2tf32((p00 * qn0 + p01 * qn1) * ATTN_SCALE));
    Q[base + 1] = __uint_as_float(f2tf32((p10 * qn0 + p11 * qn1) * ATTN_SCALE));
    K[base]     = __uint_as_float(f2tf32(p00 * kn0 + p01 * kn1));
    K[base + 1] = __uint_as_float(f2tf32(p10 * kn0 + p11 * kn1));
    if (is_tmp) {
        V[base]     = __uint_as_float(f2tf32(qn0));
        V[base + 1] = __uint_as_float(f2tf32(qn1));
    } else {
        V[base]     = __uint_as_float(f2tf32(v0));
        V[base + 1] = __uint_as_float(f2tf32(v1));
    }
}

// ---------------- flash attention on tensor cores (tf32 mma, inputs pre-rounded) ----------------
#define ATQ 64
#define ATK 64
#define ALD 68
#define ATTN_SMEM (3 * ATK * ALD * 4)

__global__ void __launch_bounds__(128) attn_tc_kernel(
        const float* __restrict__ Q, const float* __restrict__ K,
        const float* __restrict__ V, float* __restrict__ Aout) {
    extern __shared__ uint32_t dyn[];
    uint32_t (*Ks)[ALD] = (uint32_t(*)[ALD])dyn;
    uint32_t (*Vs)[ALD] = (uint32_t(*)[ALD])(dyn + ATK * ALD);
    uint32_t (*Ps)[ALD] = (uint32_t(*)[ALD])(dyn + 2 * ATK * ALD);

    int h   = blockIdx.y;
    int q0  = blockIdx.x * ATQ;
    int tid = threadIdx.x;          // 128
    int warp = tid >> 5;
    int lane = tid & 31;
    int gid  = lane >> 2;
    int tig  = lane & 3;
    int w16  = warp * 16;

    const uint32_t* Qh = (const uint32_t*)(Q + (size_t)h * L_ALL * HD);
    const uint32_t* Kh = (const uint32_t*)(K + (size_t)h * L_ALL * HD);
    const uint32_t* Vh = (const uint32_t*)(V + (size_t)h * L_ALL * HD);

    #pragma unroll
    for (int i = 0; i < 8; i++) {
        int linear = tid + i * 128;
        int r = linear >> 4;
        int c4 = (linear & 15) * 4;
        uint4 qv = *(const uint4*)(Qh + (size_t)(q0 + r) * HD + c4);
        *(uint4*)&Ps[r][c4] = qv;
    }
    __syncthreads();

    uint32_t qf[8][4];
    #pragma unroll
    for (int ks = 0; ks < 8; ks++) {
        qf[ks][0] = Ps[w16 + gid][ks * 8 + tig];
        qf[ks][1] = Ps[w16 + gid + 8][ks * 8 + tig];
        qf[ks][2] = Ps[w16 + gid][ks * 8 + tig + 4];
        qf[ks][3] = Ps[w16 + gid + 8][ks * 8 + tig + 4];
    }

    float oacc[8][4];
    #pragma unroll
    for (int nt = 0; nt < 8; nt++)
        #pragma unroll
        for (int c = 0; c < 4; c++) oacc[nt][c] = 0.f;
    float m0 = -INFINITY, m1 = -INFINITY, l0 = 0.f, l1 = 0.f;

    for (int kb = 0; kb < L_ALL; kb += ATK) {
        __syncthreads();
        #pragma unroll
        for (int i = 0; i < 8; i++) {
            int linear = tid + i * 128;
            int r = linear >> 4;
            int c4 = (linear & 15) * 4;
            uint4 kv = *(const uint4*)(Kh + (size_t)(kb + r) * HD + c4);
            uint4 vv = *(const uint4*)(Vh + (size_t)(kb + r) * HD + c4);
            *(uint4*)&Ks[r][c4] = kv;
            *(uint4*)&Vs[r][c4] = vv;
        }
        __syncthreads();

        float sacc[8][4];
        #pragma unroll
        for (int nt = 0; nt < 8; nt++)
            #pragma unroll
            for (int c = 0; c < 4; c++) sacc[nt][c] = 0.f;
        #pragma unroll
        for (int ks = 0; ks < 8; ks++) {
            #pragma unroll
            for (int nt = 0; nt < 8; nt++) {
                uint32_t b0 = Ks[nt * 8 + gid][ks * 8 + tig];
                uint32_t b1 = Ks[nt * 8 + gid][ks * 8 + tig + 4];
                mma_tf32(sacc[nt][0], sacc[nt][1], sacc[nt][2], sacc[nt][3],
                         qf[ks][0], qf[ks][1], qf[ks][2], qf[ks][3], b0, b1);
            }
        }

        float t0 = -INFINITY, t1 = -INFINITY;
        #pragma unroll
        for (int nt = 0; nt < 8; nt++) {
            t0 = fmaxf(t0, fmaxf(sacc[nt][0], sacc[nt][1]));
            t1 = fmaxf(t1, fmaxf(sacc[nt][2], sacc[nt][3]));
        }
        t0 = fmaxf(t0, __shfl_xor_sync(0xffffffffu, t0, 1));
        t0 = fmaxf(t0, __shfl_xor_sync(0xffffffffu, t0, 2));
        t1 = fmaxf(t1, __shfl_xor_sync(0xffffffffu, t1, 1));
        t1 = fmaxf(t1, __shfl_xor_sync(0xffffffffu, t1, 2));
        float mn0 = fmaxf(m0, t0), mn1 = fmaxf(m1, t1);
        float al0 = __expf(m0 - mn0), al1 = __expf(m1 - mn1);
        m0 = mn0; m1 = mn1;

        float ts0 = 0.f, ts1 = 0.f;
        #pragma unroll
        for (int nt = 0; nt < 8; nt++) {
            int c0 = nt * 8 + tig * 2;
            uint32_t p00 = f2tf32(__expf(sacc[nt][0] - mn0));
            uint32_t p01 = f2tf32(__expf(sacc[nt][1] - mn0));
            uint32_t p10 = f2tf32(__expf(sacc[nt][2] - mn1));
            uint32_t p11 = f2tf32(__expf(sacc[nt][3] - mn1));
            Ps[w16 + gid][c0]         = p00;
            Ps[w16 + gid][c0 + 1]     = p01;
            Ps[w16 + gid + 8][c0]     = p10;
            Ps[w16 + gid + 8][c0 + 1] = p11;
            ts0 += __uint_as_float(p00) + __uint_as_float(p01);
            ts1 += __uint_as_float(p10) + __uint_as_float(p11);
        }
        ts0 += __shfl_xor_sync(0xffffffffu, ts0, 1);
        ts0 += __shfl_xor_sync(0xffffffffu, ts0, 2);
        ts1 += __shfl_xor_sync(0xffffffffu, ts1, 1);
        ts1 += __shfl_xor_sync(0xffffffffu, ts1, 2);
        l0 = l0 * al0 + ts0;
        l1 = l1 * al1 + ts1;

        #pragma unroll
        for (int nt = 0; nt < 8; nt++) {
            oacc[nt][0] *= al0; oacc[nt][1] *= al0;
            oacc[nt][2] *= al1; oacc[nt][3] *= al1;
        }
        __syncwarp();

        #pragma unroll
        for (int ks = 0; ks < 8; ks++) {
            uint32_t a0 = Ps[w16 + gid][ks * 8 + tig];
            uint32_t a1 = Ps[w16 + gid + 8][ks * 8 + tig];
            uint32_t a2 = Ps[w16 + gid][ks * 8 + tig + 4];
            uint32_t a3 = Ps[w16 + gid + 8][ks * 8 + tig + 4];
            #pragma unroll
            for (int nt = 0; nt < 8; nt++) {
                uint32_t b0 = Vs[ks * 8 + tig][nt * 8 + gid];
                uint32_t b1 = Vs[ks * 8 + tig + 4][nt * 8 + gid];
                mma_tf32(oacc[nt][0], oacc[nt][1], oacc[nt][2], oacc[nt][3],
                         a0, a1, a2, a3, b0, b1);
            }
        }
        __syncwarp();
    }

    float i0 = 1.f / l0, i1 = 1.f / l1;
    int r0 = q0 + w16 + gid;
    int r1 = r0 + 8;
    #pragma unroll
    for (int nt = 0; nt < 8; nt++) {
        int c0 = h * HD + nt * 8 + tig * 2;
        Aout[(size_t)r0 * D_MODEL + c0]     = oacc[nt][0] * i0;
        Aout[(size_t)r0 * D_MODEL + c0 + 1] = oacc[nt][1] * i0;
        Aout[(size_t)r1 * D_MODEL + c0]     = oacc[nt][2] * i1;
        Aout[(size_t)r1 * D_MODEL + c0 + 1] = oacc[nt][3] * i1;
    }
}

extern "C" void kernel_launch(void* const* d_in, const int* in_sizes, int n_in,
                              void* d_out, int out_size) {
    const float* img      = (const float*)d_in[0];
    const float* temporal = (const float*)d_in[1];
    const float* txt      = (const float*)d_in[2];
    const float* vec      = (const float*)d_in[3];
    const float* pe       = (const float*)d_in[4];
    const float* mod_w    = (const float*)d_in[5];
    const float* mod_b    = (const float*)d_in[6];
    const float* qkv_w    = (const float*)d_in[7];
    const float* q_scale  = (const float*)d_in[8];
    const float* k_scale  = (const float*)d_in[9];
    const float* proj_w   = (const float*)d_in[10];
    const float* proj_b   = (const float*)d_in[11];
    const float* mlp_w1   = (const float*)d_in[12];
    const float* mlp_b1   = (const float*)d_in[13];
    const float* mlp_w2   = (const float*)d_in[14];
    const float* mlp_b2   = (const float*)d_in[15];
    float* out = (float*)d_out;

    static float *mod = 0, *xm = 0, *qkv = 0, *Qb = 0, *Kb = 0, *Vb = 0,
                 *attn = 0, *x1 = 0, *ym = 0, *hbuf = 0;
    if (!mod) {
        cudaGetSymbolAddress((void**)&mod,  g_mod);
        cudaGetSymbolAddress((void**)&xm,   g_xm);
        cudaGetSymbolAddress((void**)&qkv,  g_qkv);
        cudaGetSymbolAddress((void**)&Qb,   g_Q);
        cudaGetSymbolAddress((void**)&Kb,   g_K);
        cudaGetSymbolAddress((void**)&Vb,   g_V);
        cudaGetSymbolAddress((void**)&attn, g_attn);
        cudaGetSymbolAddress((void**)&x1,   g_x1);
        cudaGetSymbolAddress((void**)&ym,   g_ym);
        cudaGetSymbolAddress((void**)&hbuf, g_h);
        cudaFuncSetAttribute(attn_tc_kernel,
                             cudaFuncAttributeMaxDynamicSharedMemorySize, ATTN_SMEM);
        cudaFuncSetAttribute(gemm_tc_kernel,
                             cudaFuncAttributeMaxDynamicSharedMemorySize, GEMM_SMEM);
    }

    const int off_txt = 0;
    const int off_img = L_TXT;
    const int off_tmp = L_TXT + L_IMG;

    // 1. mod (silu fused)
    mod_kernel<<<(3 * 6144) / 256, 256>>>(vec, mod_w, mod_b, mod);

    // 2. LN1 + modulate
    lnmod_kernel<<<L_TXT, 256>>>(txt,      xm + (size_t)off_txt * D_MODEL, mod + 2 * 6144, mod + 2 * 6144 + 1024);
    lnmod_kernel<<<L_IMG, 256>>>(img,      xm + (size_t)off_img * D_MODEL, mod + 0,        mod + 1024);
    lnmod_kernel<<<L_TMP, 256>>>(temporal, xm + (size_t)off_tmp * D_MODEL, mod + 1 * 6144, mod + 1 * 6144 + 1024);

    // 3. QKV (batched z=3: txt->w2, img->w0, tmp->w1)
    {
        BArgs ba = {};
        int ao[3] = {off_txt, off_img, off_tmp};
        for (int z = 0; z < 3; z++) { ba.aoff[z] = ao[z]; ba.coff[z] = ao[z]; }
        ba.m[0] = 256; ba.m[1] = 1024; ba.m[2] = 1024;
        ba.woff[0] = 2LL * 1024 * 3072; ba.woff[1] = 0; ba.woff[2] = 1LL * 1024 * 3072;
        gemm_tc_kernel<<<dim3(3072 / TBN, 16, 3), 256, GEMM_SMEM>>>(xm, qkv_w, qkv, 3072, 1024,
                                                                    proj_b, mod, 0, ba);
    }

    // 4. RMS + scale + RoPE + tf32 pre-round + scatter
    qkvpost_kernel<<<(L_ALL * NH) / 8, 256>>>(qkv, pe, q_scale, k_scale, Qb, Kb, Vb);

    // 5. attention
    attn_tc_kernel<<<dim3(L_ALL / ATQ, NH), 128, ATTN_SMEM>>>(Qb, Kb, Vb, attn);

    // 6. proj + gate + residual (batched z=3; residuals read original inputs directly)
    {
        BArgs ba = {};
        int ao[3] = {off_txt, off_img, off_tmp};
        int wi[3] = {2, 0, 1};
        const float* rp[3] = {txt, img, temporal};
        for (int z = 0; z < 3; z++) {
            ba.aoff[z] = ao[z]; ba.coff[z] = ao[z]; ba.roff[z] = 0;
            ba.resp[z] = rp[z];
            ba.woff[z] = (long long)wi[z] * 1024 * 1024;
            ba.boff[z] = wi[z] * 1024;
            ba.goff[z] = wi[z] * 6144 + 2048;
        }
        ba.m[0] = 256; ba.m[1] = 1024; ba.m[2] = 1024;
        gemm_tc_kernel<<<dim3(1024 / TBN, 16, 3), 256, GEMM_SMEM>>>(attn, proj_w, x1, 1024, 1024,
                                                                    proj_b, mod, 2, ba);
    }

    // 7. img + txt MLP (batched z=2); temporal must wait for final img
    lnmod_kernel<<<L_IMG, 256>>>(x1 + (size_t)off_img * D_MODEL, ym,
                                 mod + 0 * 6144 + 3072, mod + 0 * 6144 + 4096);
    lnmod_kernel<<<L_TXT, 256>>>(x1 + (size_t)off_txt * D_MODEL, ym + (size_t)1024 * D_MODEL,
                                 mod + 2 * 6144 + 3072, mod + 2 * 6144 + 4096);
    {
        BArgs ba = {};
        ba.aoff[0] = 0;    ba.coff[0] = 0;    ba.m[0] = 1024;
        ba.woff[0] = 0;    ba.boff[0] = 0;
        ba.aoff[1] = 1024; ba.coff[1] = 1024; ba.m[1] = 256;
        ba.woff[1] = 2LL * 1024 * 4096; ba.boff[1] = 2 * 4096;
        gemm_tc_kernel<<<dim3(4096 / TBN, 16, 2), 256, GEMM_SMEM>>>(ym, mlp_w1, hbuf, 4096, 1024,
                                                                    mlp_b1, mod, 1, ba);
    }
    {
        BArgs ba = {};
        ba.aoff[0] = 0;    ba.coff[0] = 0;    ba.roff[0] = off_img; ba.resp[0] = x1; ba.m[0] = 1024;
        ba.woff[0] = 0;    ba.boff[0] = 0;    ba.goff[0] = 0 * 6144 + 5120;
        ba.aoff[1] = 1024; ba.coff[1] = 2048; ba.roff[1] = off_txt; ba.resp[1] = x1; ba.m[1] = 256;
        ba.woff[1] = 2LL * 4096 * 1024; ba.boff[1] = 2 * 1024; ba.goff[1] = 2 * 6144 + 5120;
        gemm_tc_kernel<<<dim3(1024 / TBN, 16, 2), 256, GEMM_SMEM>>>(hbuf, mlp_w2, out, 1024, 4096,
                                                                    mlp_b2, mod, 2, ba);
    }

    // 8. temporal MLP: LN of FINAL img (reference quirk), residual = x1 tmp rows
    lnmod_kernel<<<L_TMP, 256>>>(out, ym, mod + 1 * 6144 + 3072, mod + 1 * 6144 + 4096);
    {
        BArgs ba = {};
        ba.aoff[0] = 0; ba.coff[0] = 0; ba.m[0] = 1024;
        ba.woff[0] = 1LL * 1024 * 4096; ba.boff[0] = 4096;
        gemm_tc_kernel<<<dim3(4096 / TBN, 16, 1), 256, GEMM_SMEM>>>(ym, mlp_w1, hbuf, 4096, 1024,
                                                                    mlp_b1, mod, 1, ba);
    }
    {
        BArgs ba = {};
        ba.aoff[0] = 0; ba.coff[0] = 1024; ba.roff[0] = off_tmp; ba.resp[0] = x1; ba.m[0] = 1024;
        ba.woff[0] = 1LL * 4096 * 1024; ba.boff[0] = 1024; ba.goff[0] = 1 * 6144 + 5120;
        gemm_tc_kernel<<<dim3(1024 / TBN, 16, 1), 256, GEMM_SMEM>>>(hbuf, mlp_w2, out, 1024, 4096,
                                                                    mlp_b2, mod, 2, ba);
    }
}

// round 16
// speedup vs baseline: 1.3174x; 1.1321x over previous
#include <cuda_runtime.h>
#include <cuda_bf16.h>
#include <cuda_fp16.h>
#include <math.h>
#include <stdint.h>

// ---------------- problem constants ----------------
#define L_TXT 256
#define L_IMG 1024
#define L_TMP 1024
#define L_ALL 2304          // txt + img + tmp
#define D_MODEL 1024
#define NH 16
#define HD 64
#define D_MLP 4096
#define EPS 1e-6f
#define ATTN_SCALE 0.125f   // 1/sqrt(64)

// ---------------- scratch (static device memory; no allocation) ----------------
__device__ float  g_mod[3 * 6144];
__device__ float  g_xm[L_ALL * D_MODEL];
__device__ float  g_qkv[L_ALL * 3 * D_MODEL];
__device__ __half g_Q[NH * L_ALL * HD];        // [h][l][d], fp16, pre-scaled by ATTN_SCALE
__device__ __half g_K[NH * L_ALL * HD];        // [h][l][d], fp16
__device__ __half g_V[NH * HD * L_ALL];        // [h][d][l], fp16 (transposed for PV)
__device__ float  g_attn[L_ALL * D_MODEL];
__device__ float  g_x1[L_ALL * D_MODEL];
__device__ float  g_ym[1280 * D_MODEL];
__device__ float  g_h[1280 * D_MLP];

// ---------------- helpers ----------------
__device__ __forceinline__ float gelu_tanh(float x) {
    const float c = 0.7978845608028654f; // sqrt(2/pi)
    float x3 = x * x * x;
    return 0.5f * x * (1.f + tanhf(c * (x + 0.044715f * x3)));
}

__device__ __forceinline__ uint32_t pack_h2(float a, float b) {
    __half2 h = __floats2half2_rn(a, b);
    return *(uint32_t*)&h;
}

__device__ __forceinline__ void mma_f16(float& d0, float& d1, float& d2, float& d3,
                                        uint32_t a0, uint32_t a1, uint32_t a2, uint32_t a3,
                                        uint32_t b0, uint32_t b1) {
    asm volatile(
        "mma.sync.aligned.m16n8k16.row.col.f32.f16.f16.f32 "
        "{%0,%1,%2,%3}, {%4,%5,%6,%7}, {%8,%9}, {%0,%1,%2,%3};"
        : "+f"(d0), "+f"(d1), "+f"(d2), "+f"(d3)
        : "r"(a0), "r"(a1), "r"(a2), "r"(a3), "r"(b0), "r"(b1));
}

// ---------------- mod = silu(vec) @ mod_w + mod_b  (silu fused) ----------------
__global__ void mod_kernel(const float* __restrict__ vecp, const float* __restrict__ mod_w,
                           const float* __restrict__ mod_b, float* __restrict__ mod) {
    __shared__ float s_sv[D_MODEL];
    for (int i = threadIdx.x; i < D_MODEL; i += 256) {
        float x = vecp[i];
        s_sv[i] = x / (1.f + expf(-x));
    }
    __syncthreads();
    int o = blockIdx.x * 256 + threadIdx.x;
    int i = o / 6144;
    int j = o - i * 6144;
    const float* w = mod_w + (size_t)i * D_MODEL * 6144 + j;
    float acc = 0.f;
    #pragma unroll 8
    for (int d = 0; d < D_MODEL; ++d) acc = fmaf(s_sv[d], w[(size_t)d * 6144], acc);
    mod[o] = acc + mod_b[o];
}

// ---------------- LN + modulate: out = (1+sc)*ln(x) + sh ----------------
__global__ void lnmod_kernel(const float* __restrict__ x, float* __restrict__ out,
                             const float* __restrict__ sh, const float* __restrict__ sc) {
    int r = blockIdx.x;
    const float* xr = x + (size_t)r * D_MODEL;
    int t = threadIdx.x; // 256
    float v[4]; float sum = 0.f, sq = 0.f;
    #pragma unroll
    for (int i = 0; i < 4; i++) { float f = xr[t + i * 256]; v[i] = f; sum += f; sq += f * f; }
    #pragma unroll
    for (int o = 16; o; o >>= 1) {
        sum += __shfl_xor_sync(0xffffffffu, sum, o);
        sq  += __shfl_xor_sync(0xffffffffu, sq, o);
    }
    __shared__ float ssum[8], ssq[8];
    int w = t >> 5, lane = t & 31;
    if (lane == 0) { ssum[w] = sum; ssq[w] = sq; }
    __syncthreads();
    if (t == 0) {
        float S = 0.f, Q = 0.f;
        #pragma unroll
        for (int i = 0; i < 8; i++) { S += ssum[i]; Q += ssq[i]; }
        float mean = S * (1.f / D_MODEL);
        float var  = Q * (1.f / D_MODEL) - mean * mean;
        ssum[0] = mean; ssq[0] = rsqrtf(var + EPS);
    }
    __syncthreads();
    float mean = ssum[0], inv = ssq[0];
    float* orow = out + (size_t)r * D_MODEL;
    #pragma unroll
    for (int i = 0; i < 4; i++) {
        int d = t + i * 256;
        orow[d] = (1.f + sc[d]) * ((v[i] - mean) * inv) + sh[d];
    }
}

// ---------------- fp16 tensor-core GEMM, 64x128x32 tiles (round-15 proven) ----------------
#define TBM 64
#define TBN 128
#define TBK 32
#define A_HEX 516
#define A_STAGE (2 * A_HEX)
#define B_NB 66
#define B_HEX 1058
#define B_STAGE (2 * B_HEX)
#define GEMM_SMEM ((2 * A_STAGE + 2 * B_STAGE) * 4)   // 25184 bytes

struct BArgs {
    const float* resp[3];
    int aoff[3];
    int coff[3];
    int roff[3];
    int m[3];
    long long woff[3];
    int boff[3];
    int goff[3];
};

__global__ void __launch_bounds__(256) gemm_tc_kernel(
        const float* __restrict__ A, const float* __restrict__ W,
        float* __restrict__ C, int N, int K,
        const float* __restrict__ bias,
        const float* __restrict__ gate,
        int epi, BArgs ba) {
    int z = blockIdx.z;
    int brow = blockIdx.y, bcol = blockIdx.x;
    if (brow * TBM >= ba.m[z]) return;

    extern __shared__ uint32_t gsm[];
    uint32_t (*As)[A_STAGE] = (uint32_t(*)[A_STAGE])gsm;
    uint32_t (*Bs)[B_STAGE] = (uint32_t(*)[B_STAGE])(gsm + 2 * A_STAGE);

    int tid  = threadIdx.x;
    int warp = tid >> 5;
    int lane = tid & 31;
    int gid  = lane >> 2;
    int tig  = lane & 3;
    int wm2  = (warp >> 2) * 2;
    int wn8  = (warp & 3) * 4;

    const float* Ab = A + (size_t)ba.aoff[z] * K;
    const float* Bb = W + ba.woff[z];

    int al0 = tid, al1 = tid + 256;
    int a_row0 = al0 >> 3, a_kq0 = (al0 & 7) * 4;
    int a_row1 = al1 >> 3, a_kq1 = (al1 & 7) * 4;
    int kp0a = (a_kq0 >> 1) & 7, hex0a = a_kq0 >> 4;
    int kp1a = (a_kq1 >> 1) & 7, hex1a = a_kq1 >> 4;
    int abase0 = hex0a * A_HEX + (a_row0 >> 4) * 128 + (a_row0 & 7) * 16
               + ((a_row0 >> 3) & 1) * 2 + ((kp0a >> 2) & 1) + (kp0a & 3) * 4;
    int abase1 = hex1a * A_HEX + (a_row1 >> 4) * 128 + (a_row1 & 7) * 16
               + ((a_row1 >> 3) & 1) * 2 + ((kp1a >> 2) & 1) + (kp1a & 3) * 4;

    int b_row = tid >> 6;
    int b_col = (tid & 63) * 2;
    int n7  = b_col & 7;
    int nbl = b_col >> 3;

    const float* Aptr0 = Ab + (size_t)(brow * TBM + a_row0) * K + a_kq0;
    const float* Aptr1 = Ab + (size_t)(brow * TBM + a_row1) * K + a_kq1;
    const float* Bptr  = Bb + (size_t)b_row * N + bcol * TBN + b_col;

    float acc[2][4][4];
    #pragma unroll
    for (int i = 0; i < 2; i++)
        #pragma unroll
        for (int j = 0; j < 4; j++)
            #pragma unroll
            for (int c = 0; c < 4; c++) acc[i][j][c] = 0.f;

    int iters = K / TBK;

    float4 av0 = *(const float4*)(Aptr0);
    float4 av1 = *(const float4*)(Aptr1);
    float2 bv[8];
    #pragma unroll
    for (int r = 0; r < 8; r++)
        bv[r] = *(const float2*)(Bptr + (size_t)(r * 4) * N);

    #define STORE_TILE(BUF) do {                                                     \
        As[BUF][abase0]     = pack_h2(av0.x, av0.y);                                 \
        As[BUF][abase0 + 4] = pack_h2(av0.z, av0.w);                                 \
        As[BUF][abase1]     = pack_h2(av1.x, av1.y);                                 \
        As[BUF][abase1 + 4] = pack_h2(av1.z, av1.w);                                 \
        _Pragma("unroll")                                                            \
        for (int r = 0; r < 8; r++) {                                                \
            int k   = b_row + r * 4;                                                 \
            int hex = k >> 4;                                                        \
            int kp  = (k >> 1) & 7;                                                  \
            int sl  = (kp >> 2) & 1;                                                 \
            int jm  = kp & 3;                                                        \
            int par = k & 1;                                                         \
            uint32_t* bb = &Bs[BUF][hex * B_HEX + nbl * B_NB + sl];                  \
            ((__half*)&bb[(n7 * 4 + jm) * 2])[par]       = __float2half_rn(bv[r].x);\
            ((__half*)&bb[((n7 + 1) * 4 + jm) * 2])[par] = __float2half_rn(bv[r].y);\
        }                                                                            \
    } while (0)

    STORE_TILE(0);
    __syncthreads();

    for (int it = 0; it < iters; ++it) {
        int cur = it & 1;
        if (it + 1 < iters) {
            int k0 = (it + 1) * TBK;
            av0 = *(const float4*)(Aptr0 + k0);
            av1 = *(const float4*)(Aptr1 + k0);
            #pragma unroll
            for (int r = 0; r < 8; r++)
                bv[r] = *(const float2*)(Bptr + (size_t)(k0 + r * 4) * N);
        }

        #pragma unroll
        for (int hex = 0; hex < 2; hex++) {
            uint4 ua[2];
            #pragma unroll
            for (int mt = 0; mt < 2; mt++)
                ua[mt] = *(const uint4*)&As[cur][hex * A_HEX + (wm2 + mt) * 128 + lane * 4];
            uint2 ub[4];
            #pragma unroll
            for (int nt = 0; nt < 4; nt++)
                ub[nt] = *(const uint2*)&Bs[cur][hex * B_HEX + (wn8 + nt) * B_NB + lane * 2];
            #pragma unroll
            for (int mt = 0; mt < 2; mt++)
                #pragma unroll
                for (int nt = 0; nt < 4; nt++)
                    mma_f16(acc[mt][nt][0], acc[mt][nt][1], acc[mt][nt][2], acc[mt][nt][3],
                            ua[mt].x, ua[mt].z, ua[mt].y, ua[mt].w,
                            ub[nt].x, ub[nt].y);
        }

        if (it + 1 < iters) {
            int nxt = cur ^ 1;
            STORE_TILE(nxt);
            __syncthreads();
        }
    }
    #undef STORE_TILE

    // epilogue
    int wm = (warp >> 2) * 32;
    int wn = (warp & 3) * 32;
    int crow = ba.coff[z];
    int rrow = ba.roff[z];
    const float* resz = ba.resp[z];
    int bo = ba.boff[z], go = ba.goff[z];
    #pragma unroll
    for (int mt = 0; mt < 2; mt++) {
        int lrow0 = brow * TBM + wm + mt * 16 + gid;
        int lrow1 = lrow0 + 8;
        #pragma unroll
        for (int nt = 0; nt < 4; nt++) {
            int col0 = bcol * TBN + wn + nt * 8 + tig * 2;
            int col1 = col0 + 1;
            float v0 = acc[mt][nt][0], v1 = acc[mt][nt][1];
            float v2 = acc[mt][nt][2], v3 = acc[mt][nt][3];
            if (epi == 1) {
                v0 = gelu_tanh(v0 + bias[bo + col0]); v1 = gelu_tanh(v1 + bias[bo + col1]);
                v2 = gelu_tanh(v2 + bias[bo + col0]); v3 = gelu_tanh(v3 + bias[bo + col1]);
            } else if (epi == 2) {
                v0 = resz[(size_t)(rrow + lrow0) * N + col0] + gate[go + col0] * (v0 + bias[bo + col0]);
                v1 = resz[(size_t)(rrow + lrow0) * N + col1] + gate[go + col1] * (v1 + bias[bo + col1]);
                v2 = resz[(size_t)(rrow + lrow1) * N + col0] + gate[go + col0] * (v2 + bias[bo + col0]);
                v3 = resz[(size_t)(rrow + lrow1) * N + col1] + gate[go + col1] * (v3 + bias[bo + col1]);
            }
            C[(size_t)(crow + lrow0) * N + col0] = v0;
            C[(size_t)(crow + lrow0) * N + col1] = v1;
            C[(size_t)(crow + lrow1) * N + col0] = v2;
            C[(size_t)(crow + lrow1) * N + col1] = v3;
        }
    }
}

// ---------------- QKV post: RMS + scale + RoPE + fp16 pack + scatter ----------------
// Q/K: [h][l][d] half2-packed; Q pre-scaled by ATTN_SCALE. V: [h][d][l] (transposed).
__global__ void qkvpost_kernel(const float* __restrict__ Y, const float* __restrict__ pe,
                               const float* __restrict__ q_scale, const float* __restrict__ k_scale,
                               __half2* __restrict__ Q, __half2* __restrict__ K,
                               __half* __restrict__ V) {
    int gw = blockIdx.x * 8 + (threadIdx.x >> 5);
    int lane = threadIdx.x & 31;
    int l = gw >> 4;
    int h = gw & 15;
    int i = (l < L_TXT) ? 2 : (l < (L_TXT + L_IMG) ? 0 : 1);
    bool is_tmp = (l >= L_TXT + L_IMG);

    const float* row = Y + (size_t)l * 3072 + h * HD;
    float q0 = row[2 * lane],        q1 = row[2 * lane + 1];
    float k0 = row[1024 + 2 * lane], k1 = row[1024 + 2 * lane + 1];
    float v0 = row[2048 + 2 * lane], v1 = row[2048 + 2 * lane + 1];

    float qs = q0 * q0 + q1 * q1;
    float ks = k0 * k0 + k1 * k1;
    #pragma unroll
    for (int o = 16; o; o >>= 1) {
        qs += __shfl_xor_sync(0xffffffffu, qs, o);
        ks += __shfl_xor_sync(0xffffffffu, ks, o);
    }
    float qinv = rsqrtf(qs * (1.f / HD) + EPS);
    float kinv = rsqrtf(ks * (1.f / HD) + EPS);

    float qn0 = q0 * qinv * q_scale[i * HD + 2 * lane];
    float qn1 = q1 * qinv * q_scale[i * HD + 2 * lane + 1];
    float kn0 = k0 * kinv * k_scale[i * HD + 2 * lane];
    float kn1 = k1 * kinv * k_scale[i * HD + 2 * lane + 1];

    const float* p = pe + ((size_t)l * 32 + lane) * 4;
    float p00 = p[0], p01 = p[1], p10 = p[2], p11 = p[3];

    size_t w2 = ((size_t)h * L_ALL + l) * 32 + lane;      // half2 index
    Q[w2] = __floats2half2_rn((p00 * qn0 + p01 * qn1) * ATTN_SCALE,
                              (p10 * qn0 + p11 * qn1) * ATTN_SCALE);
    K[w2] = __floats2half2_rn(p00 * kn0 + p01 * kn1,
                              p10 * kn0 + p11 * kn1);
    float vo0, vo1;
    if (is_tmp) { vo0 = qn0; vo1 = qn1; }   // reference quirk: v = pre-RoPE RMS'd q
    else        { vo0 = v0;  vo1 = v1;  }
    size_t vbase = ((size_t)h * HD + 2 * lane) * L_ALL + l;
    V[vbase]         = __float2half_rn(vo0);
    V[vbase + L_ALL] = __float2half_rn(vo1);
}

// ---------------- flash attention, fp16 mma m16n8k16 ----------------
// 64 q-rows/block, 4 warps x 16 rows; 64-key tiles. Word = half2 of 2 k-elems.
#define ATQ 64
#define ATK 64
#define ALD2 36                        // half2 words per row (32 + pad 4) -> conflict-free
#define ATTN_SMEM (3 * 64 * ALD2 * 4)  // 27648 bytes

__global__ void __launch_bounds__(128) attn_tc_kernel(
        const __half* __restrict__ Q, const __half* __restrict__ K,
        const __half* __restrict__ V, float* __restrict__ Aout) {
    extern __shared__ uint32_t dyn[];
    uint32_t (*Ks)[ALD2] = (uint32_t(*)[ALD2])dyn;                  // [key][d-pair]
    uint32_t (*Vt)[ALD2] = (uint32_t(*)[ALD2])(dyn + 64 * ALD2);    // [d][key-pair]
    uint32_t (*Ps)[ALD2] = (uint32_t(*)[ALD2])(dyn + 2 * 64 * ALD2);// Q staging / P

    int h   = blockIdx.y;
    int q0  = blockIdx.x * ATQ;
    int tid = threadIdx.x;          // 128
    int warp = tid >> 5;
    int lane = tid & 31;
    int gid  = lane >> 2;
    int tig  = lane & 3;
    int w16  = warp * 16;

    const uint32_t* Qh = (const uint32_t*)(Q + (size_t)h * L_ALL * HD);   // row: 32 words
    const uint32_t* Kh = (const uint32_t*)(K + (size_t)h * L_ALL * HD);
    const uint32_t* Vh = (const uint32_t*)(V + (size_t)h * HD * L_ALL);   // row: 1152 words

    // stage Q: 64 rows x 8 uint4
    #pragma unroll
    for (int i = 0; i < 4; i++) {
        int linear = tid + i * 128;
        int r = linear >> 3;
        int c4 = (linear & 7) * 4;
        uint4 qv = *(const uint4*)(Qh + (size_t)(q0 + r) * 32 + c4);
        *(uint4*)&Ps[r][c4] = qv;
    }
    __syncthreads();

    // Q fragments: 4 k-steps (d = 64 / 16)
    uint32_t qf[4][4];
    #pragma unroll
    for (int ks = 0; ks < 4; ks++) {
        qf[ks][0] = Ps[w16 + gid][ks * 8 + tig];
        qf[ks][1] = Ps[w16 + gid + 8][ks * 8 + tig];
        qf[ks][2] = Ps[w16 + gid][ks * 8 + tig + 4];
        qf[ks][3] = Ps[w16 + gid + 8][ks * 8 + tig + 4];
    }

    float oacc[8][4];
    #pragma unroll
    for (int nt = 0; nt < 8; nt++)
        #pragma unroll
        for (int c = 0; c < 4; c++) oacc[nt][c] = 0.f;
    float m0 = -INFINITY, m1 = -INFINITY, l0 = 0.f, l1 = 0.f;

    for (int kb = 0; kb < L_ALL; kb += ATK) {
        __syncthreads();
        // K tile: 64 keys x 32 words; V tile (transposed): 64 d x 32 key-words
        #pragma unroll
        for (int i = 0; i < 4; i++) {
            int linear = tid + i * 128;
            int r = linear >> 3;
            int c4 = (linear & 7) * 4;
            uint4 kv = *(const uint4*)(Kh + (size_t)(kb + r) * 32 + c4);
            uint4 vv = *(const uint4*)(Vh + (size_t)r * (L_ALL / 2) + (kb >> 1) + c4);
            *(uint4*)&Ks[r][c4] = kv;
            *(uint4*)&Vt[r][c4] = vv;
        }
        __syncthreads();

        // S = Q @ K^T : 4 k-steps x 8 n-tiles
        float sacc[8][4];
        #pragma unroll
        for (int nt = 0; nt < 8; nt++)
            #pragma unroll
            for (int c = 0; c < 4; c++) sacc[nt][c] = 0.f;
        #pragma unroll
        for (int ks = 0; ks < 4; ks++) {
            #pragma unroll
            for (int nt = 0; nt < 8; nt++) {
                uint32_t b0 = Ks[nt * 8 + gid][ks * 8 + tig];
                uint32_t b1 = Ks[nt * 8 + gid][ks * 8 + tig + 4];
                mma_f16(sacc[nt][0], sacc[nt][1], sacc[nt][2], sacc[nt][3],
                        qf[ks][0], qf[ks][1], qf[ks][2], qf[ks][3], b0, b1);
            }
        }

        float t0 = -INFINITY, t1 = -INFINITY;
        #pragma unroll
        for (int nt = 0; nt < 8; nt++) {
            t0 = fmaxf(t0, fmaxf(sacc[nt][0], sacc[nt][1]));
            t1 = fmaxf(t1, fmaxf(sacc[nt][2], sacc[nt][3]));
        }
        t0 = fmaxf(t0, __shfl_xor_sync(0xffffffffu, t0, 1));
        t0 = fmaxf(t0, __shfl_xor_sync(0xffffffffu, t0, 2));
        t1 = fmaxf(t1, __shfl_xor_sync(0xffffffffu, t1, 1));
        t1 = fmaxf(t1, __shfl_xor_sync(0xffffffffu, t1, 2));
        float mn0 = fmaxf(m0, t0), mn1 = fmaxf(m1, t1);
        float al0 = __expf(m0 - mn0), al1 = __expf(m1 - mn1);
        m0 = mn0; m1 = mn1;

        float ts0 = 0.f, ts1 = 0.f;
        #pragma unroll
        for (int nt = 0; nt < 8; nt++) {
            // cols nt*8 + tig*2, +1 -> P word index nt*4 + tig
            __half2 h0 = __floats2half2_rn(__expf(sacc[nt][0] - mn0), __expf(sacc[nt][1] - mn0));
            __half2 h1 = __floats2half2_rn(__expf(sacc[nt][2] - mn1), __expf(sacc[nt][3] - mn1));
            Ps[w16 + gid][nt * 4 + tig]     = *(uint32_t*)&h0;
            Ps[w16 + gid + 8][nt * 4 + tig] = *(uint32_t*)&h1;
            float2 f0 = __half22float2(h0), f1 = __half22float2(h1);
            ts0 += f0.x + f0.y;
            ts1 += f1.x + f1.y;
        }
        ts0 += __shfl_xor_sync(0xffffffffu, ts0, 1);
        ts0 += __shfl_xor_sync(0xffffffffu, ts0, 2);
        ts1 += __shfl_xor_sync(0xffffffffu, ts1, 1);
        ts1 += __shfl_xor_sync(0xffffffffu, ts1, 2);
        l0 = l0 * al0 + ts0;
        l1 = l1 * al1 + ts1;

        #pragma unroll
        for (int nt = 0; nt < 8; nt++) {
            oacc[nt][0] *= al0; oacc[nt][1] *= al0;
            oacc[nt][2] *= al1; oacc[nt][3] *= al1;
        }
        __syncwarp();

        // O += P @ V : k = 64 keys -> 4 k-steps; B from transposed Vt
        #pragma unroll
        for (int ks = 0; ks < 4; ks++) {
            uint32_t a0 = Ps[w16 + gid][ks * 8 + tig];
            uint32_t a1 = Ps[w16 + gid + 8][ks * 8 + tig];
            uint32_t a2 = Ps[w16 + gid][ks * 8 + tig + 4];
            uint32_t a3 = Ps[w16 + gid + 8][ks * 8 + tig + 4];
            #pragma unroll
            for (int nt = 0; nt < 8; nt++) {
                uint32_t b0 = Vt[nt * 8 + gid][ks * 8 + tig];
                uint32_t b1 = Vt[nt * 8 + gid][ks * 8 + tig + 4];
                mma_f16(oacc[nt][0], oacc[nt][1], oacc[nt][2], oacc[nt][3],
                        a0, a1, a2, a3, b0, b1);
            }
        }
        __syncwarp();
    }

    float i0 = 1.f / l0, i1 = 1.f / l1;
    int r0 = q0 + w16 + gid;
    int r1 = r0 + 8;
    #pragma unroll
    for (int nt = 0; nt < 8; nt++) {
        int c0 = h * HD + nt * 8 + tig * 2;
        Aout[(size_t)r0 * D_MODEL + c0]     = oacc[nt][0] * i0;
        Aout[(size_t)r0 * D_MODEL + c0 + 1] = oacc[nt][1] * i0;
        Aout[(size_t)r1 * D_MODEL + c0]     = oacc[nt][2] * i1;
        Aout[(size_t)r1 * D_MODEL + c0 + 1] = oacc[nt][3] * i1;
    }
}

extern "C" void kernel_launch(void* const* d_in, const int* in_sizes, int n_in,
                              void* d_out, int out_size) {
    const float* img      = (const float*)d_in[0];
    const float* temporal = (const float*)d_in[1];
    const float* txt      = (const float*)d_in[2];
    const float* vec      = (const float*)d_in[3];
    const float* pe       = (const float*)d_in[4];
    const float* mod_w    = (const float*)d_in[5];
    const float* mod_b    = (const float*)d_in[6];
    const float* qkv_w    = (const float*)d_in[7];
    const float* q_scale  = (const float*)d_in[8];
    const float* k_scale  = (const float*)d_in[9];
    const float* proj_w   = (const float*)d_in[10];
    const float* proj_b   = (const float*)d_in[11];
    const float* mlp_w1   = (const float*)d_in[12];
    const float* mlp_b1   = (const float*)d_in[13];
    const float* mlp_w2   = (const float*)d_in[14];
    const float* mlp_b2   = (const float*)d_in[15];
    float* out = (float*)d_out;

    static float *mod = 0, *xm = 0, *qkv = 0, *attn = 0, *x1 = 0, *ym = 0, *hbuf = 0;
    static __half *Qb = 0, *Kb = 0, *Vb = 0;
    if (!mod) {
        cudaGetSymbolAddress((void**)&mod,  g_mod);
        cudaGetSymbolAddress((void**)&xm,   g_xm);
        cudaGetSymbolAddress((void**)&qkv,  g_qkv);
        cudaGetSymbolAddress((void**)&Qb,   g_Q);
        cudaGetSymbolAddress((void**)&Kb,   g_K);
        cudaGetSymbolAddress((void**)&Vb,   g_V);
        cudaGetSymbolAddress((void**)&attn, g_attn);
        cudaGetSymbolAddress((void**)&x1,   g_x1);
        cudaGetSymbolAddress((void**)&ym,   g_ym);
        cudaGetSymbolAddress((void**)&hbuf, g_h);
        cudaFuncSetAttribute(attn_tc_kernel,
                             cudaFuncAttributeMaxDynamicSharedMemorySize, ATTN_SMEM);
        cudaFuncSetAttribute(gemm_tc_kernel,
                             cudaFuncAttributeMaxDynamicSharedMemorySize, GEMM_SMEM);
    }

    const int off_txt = 0;
    const int off_img = L_TXT;
    const int off_tmp = L_TXT + L_IMG;

    // 1. mod (silu fused)
    mod_kernel<<<(3 * 6144) / 256, 256>>>(vec, mod_w, mod_b, mod);

    // 2. LN1 + modulate
    lnmod_kernel<<<L_TXT, 256>>>(txt,      xm + (size_t)off_txt * D_MODEL, mod + 2 * 6144, mod + 2 * 6144 + 1024);
    lnmod_kernel<<<L_IMG, 256>>>(img,      xm + (size_t)off_img * D_MODEL, mod + 0,        mod + 1024);
    lnmod_kernel<<<L_TMP, 256>>>(temporal, xm + (size_t)off_tmp * D_MODEL, mod + 1 * 6144, mod + 1 * 6144 + 1024);

    // 3. QKV (batched z=3: txt->w2, img->w0, tmp->w1)
    {
        BArgs ba = {};
        int ao[3] = {off_txt, off_img, off_tmp};
        for (int z = 0; z < 3; z++) { ba.aoff[z] = ao[z]; ba.coff[z] = ao[z]; }
        ba.m[0] = 256; ba.m[1] = 1024; ba.m[2] = 1024;
        ba.woff[0] = 2LL * 1024 * 3072; ba.woff[1] = 0; ba.woff[2] = 1LL * 1024 * 3072;
        gemm_tc_kernel<<<dim3(3072 / TBN, 16, 3), 256, GEMM_SMEM>>>(xm, qkv_w, qkv, 3072, 1024,
                                                                    proj_b, mod, 0, ba);
    }

    // 4. RMS + scale + RoPE + fp16 pack + scatter
    qkvpost_kernel<<<(L_ALL * NH) / 8, 256>>>(qkv, pe, q_scale, k_scale,
                                              (__half2*)Qb, (__half2*)Kb, Vb);

    // 5. attention (fp16 mma)
    attn_tc_kernel<<<dim3(L_ALL / ATQ, NH), 128, ATTN_SMEM>>>(Qb, Kb, Vb, attn);

    // 6. proj + gate + residual (batched z=3)
    {
        BArgs ba = {};
        int ao[3] = {off_txt, off_img, off_tmp};
        int wi[3] = {2, 0, 1};
        const float* rp[3] = {txt, img, temporal};
        for (int z = 0; z < 3; z++) {
            ba.aoff[z] = ao[z]; ba.coff[z] = ao[z]; ba.roff[z] = 0;
            ba.resp[z] = rp[z];
            ba.woff[z] = (long long)wi[z] * 1024 * 1024;
            ba.boff[z] = wi[z] * 1024;
            ba.goff[z] = wi[z] * 6144 + 2048;
        }
        ba.m[0] = 256; ba.m[1] = 1024; ba.m[2] = 1024;
        gemm_tc_kernel<<<dim3(1024 / TBN, 16, 3), 256, GEMM_SMEM>>>(attn, proj_w, x1, 1024, 1024,
                                                                    proj_b, mod, 2, ba);
    }

    // 7. img + txt MLP (batched z=2); temporal must wait for final img
    lnmod_kernel<<<L_IMG, 256>>>(x1 + (size_t)off_img * D_MODEL, ym,
                                 mod + 0 * 6144 + 3072, mod + 0 * 6144 + 4096);
    lnmod_kernel<<<L_TXT, 256>>>(x1 + (size_t)off_txt * D_MODEL, ym + (size_t)1024 * D_MODEL,
                                 mod + 2 * 6144 + 3072, mod + 2 * 6144 + 4096);
    {
        BArgs ba = {};
        ba.aoff[0] = 0;    ba.coff[0] = 0;    ba.m[0] = 1024;
        ba.woff[0] = 0;    ba.boff[0] = 0;
        ba.aoff[1] = 1024; ba.coff[1] = 1024; ba.m[1] = 256;
        ba.woff[1] = 2LL * 1024 * 4096; ba.boff[1] = 2 * 4096;
        gemm_tc_kernel<<<dim3(4096 / TBN, 16, 2), 256, GEMM_SMEM>>>(ym, mlp_w1, hbuf, 4096, 1024,
                                                                    mlp_b1, mod, 1, ba);
    }
    {
        BArgs ba = {};
        ba.aoff[0] = 0;    ba.coff[0] = 0;    ba.roff[0] = off_img; ba.resp[0] = x1; ba.m[0] = 1024;
        ba.woff[0] = 0;    ba.boff[0] = 0;    ba.goff[0] = 0 * 6144 + 5120;
        ba.aoff[1] = 1024; ba.coff[1] = 2048; ba.roff[1] = off_txt; ba.resp[1] = x1; ba.m[1] = 256;
        ba.woff[1] = 2LL * 4096 * 1024; ba.boff[1] = 2 * 1024; ba.goff[1] = 2 * 6144 + 5120;
        gemm_tc_kernel<<<dim3(1024 / TBN, 16, 2), 256, GEMM_SMEM>>>(hbuf, mlp_w2, out, 1024, 4096,
                                                                    mlp_b2, mod, 2, ba);
    }

    // 8. temporal MLP: LN of FINAL img (reference quirk), residual = x1 tmp rows
    lnmod_kernel<<<L_TMP, 256>>>(out, ym, mod + 1 * 6144 + 3072, mod + 1 * 6144 + 4096);
    {
        BArgs ba = {};
        ba.aoff[0] = 0; ba.coff[0] = 0; ba.m[0] = 1024;
        ba.woff[0] = 1LL * 1024 * 4096; ba.boff[0] = 4096;
        gemm_tc_kernel<<<dim3(4096 / TBN, 16, 1), 256, GEMM_SMEM>>>(ym, mlp_w1, hbuf, 4096, 1024,
                                                                    mlp_b1, mod, 1, ba);
    }
    {
        BArgs ba = {};
        ba.aoff[0] = 0; ba.coff[0] = 1024; ba.roff[0] = off_tmp; ba.resp[0] = x1; ba.m[0] = 1024;
        ba.woff[0] = 1LL * 4096 * 1024; ba.boff[0] = 1024; ba.goff[0] = 1 * 6144 + 5120;
        gemm_tc_kernel<<<dim3(1024 / TBN, 16, 1), 256, GEMM_SMEM>>>(hbuf, mlp_w2, out, 1024, 4096,
                                                                    mlp_b2, mod, 2, ba);
    }
}

// round 17
// speedup vs baseline: 1.3514x; 1.0257x over previous
#include <cuda_runtime.h>
#include <cuda_bf16.h>
#include <cuda_fp16.h>
#include <math.h>
#include <stdint.h>

// ---------------- problem constants ----------------
#define L_TXT 256
#define L_IMG 1024
#define L_TMP 1024
#define L_ALL 2304          // txt + img + tmp
#define D_MODEL 1024
#define NH 16
#define HD 64
#define D_MLP 4096
#define EPS 1e-6f
#define ATTN_SCALE 0.125f   // 1/sqrt(64)

// ---------------- scratch (static device memory; no allocation) ----------------
__device__ float  g_mod[3 * 6144];
__device__ float  g_xm[L_ALL * D_MODEL];
__device__ float  g_qkv[L_ALL * 3 * D_MODEL];
__device__ __half g_Q[NH * L_ALL * HD];        // [h][l][d], fp16, pre-scaled by ATTN_SCALE
__device__ __half g_K[NH * L_ALL * HD];        // [h][l][d], fp16
__device__ __half g_V[NH * HD * L_ALL];        // [h][d][l], fp16 (transposed for PV)
__device__ float  g_attn[L_ALL * D_MODEL];
__device__ float  g_x1[L_ALL * D_MODEL];
__device__ float  g_ym[1280 * D_MODEL];
__device__ float  g_h[1280 * D_MLP];

// ---------------- helpers ----------------
__device__ __forceinline__ float gelu_tanh(float x) {
    const float c = 0.7978845608028654f; // sqrt(2/pi)
    float x3 = x * x * x;
    return 0.5f * x * (1.f + tanhf(c * (x + 0.044715f * x3)));
}

__device__ __forceinline__ uint32_t pack_h2(float a, float b) {
    __half2 h = __floats2half2_rn(a, b);
    return *(uint32_t*)&h;
}

__device__ __forceinline__ void mma_f16(float& d0, float& d1, float& d2, float& d3,
                                        uint32_t a0, uint32_t a1, uint32_t a2, uint32_t a3,
                                        uint32_t b0, uint32_t b1) {
    asm volatile(
        "mma.sync.aligned.m16n8k16.row.col.f32.f16.f16.f32 "
        "{%0,%1,%2,%3}, {%4,%5,%6,%7}, {%8,%9}, {%0,%1,%2,%3};"
        : "+f"(d0), "+f"(d1), "+f"(d2), "+f"(d3)
        : "r"(a0), "r"(a1), "r"(a2), "r"(a3), "r"(b0), "r"(b1));
}

// ---------------- mod = silu(vec) @ mod_w + mod_b  (silu fused) ----------------
__global__ void mod_kernel(const float* __restrict__ vecp, const float* __restrict__ mod_w,
                           const float* __restrict__ mod_b, float* __restrict__ mod) {
    __shared__ float s_sv[D_MODEL];
    for (int i = threadIdx.x; i < D_MODEL; i += 256) {
        float x = vecp[i];
        s_sv[i] = x / (1.f + expf(-x));
    }
    __syncthreads();
    int o = blockIdx.x * 256 + threadIdx.x;
    int i = o / 6144;
    int j = o - i * 6144;
    const float* w = mod_w + (size_t)i * D_MODEL * 6144 + j;
    float acc = 0.f;
    #pragma unroll 8
    for (int d = 0; d < D_MODEL; ++d) acc = fmaf(s_sv[d], w[(size_t)d * 6144], acc);
    mod[o] = acc + mod_b[o];
}

// ---------------- LN + modulate: out = (1+sc)*ln(x) + sh ----------------
__global__ void lnmod_kernel(const float* __restrict__ x, float* __restrict__ out,
                             const float* __restrict__ sh, const float* __restrict__ sc) {
    int r = blockIdx.x;
    const float* xr = x + (size_t)r * D_MODEL;
    int t = threadIdx.x; // 256
    float v[4]; float sum = 0.f, sq = 0.f;
    #pragma unroll
    for (int i = 0; i < 4; i++) { float f = xr[t + i * 256]; v[i] = f; sum += f; sq += f * f; }
    #pragma unroll
    for (int o = 16; o; o >>= 1) {
        sum += __shfl_xor_sync(0xffffffffu, sum, o);
        sq  += __shfl_xor_sync(0xffffffffu, sq, o);
    }
    __shared__ float ssum[8], ssq[8];
    int w = t >> 5, lane = t & 31;
    if (lane == 0) { ssum[w] = sum; ssq[w] = sq; }
    __syncthreads();
    if (t == 0) {
        float S = 0.f, Q = 0.f;
        #pragma unroll
        for (int i = 0; i < 8; i++) { S += ssum[i]; Q += ssq[i]; }
        float mean = S * (1.f / D_MODEL);
        float var  = Q * (1.f / D_MODEL) - mean * mean;
        ssum[0] = mean; ssq[0] = rsqrtf(var + EPS);
    }
    __syncthreads();
    float mean = ssum[0], inv = ssq[0];
    float* orow = out + (size_t)r * D_MODEL;
    #pragma unroll
    for (int i = 0; i < 4; i++) {
        int d = t + i * 256;
        orow[d] = (1.f + sc[d]) * ((v[i] - mean) * inv) + sh[d];
    }
}

// ---------------- fp16 tensor-core GEMM, 128x128x32 tiles ----------------
// 8 warps (2x4), warp tile 64x32. Word layout identical to proven 64-tile
// version; mblk index extended 4 -> 8.
#define TBM 128
#define TBN 128
#define TBK 32
#define A_HEX 1028          // 8 mblk * 128 words + 4 pad (16B aligned)
#define A_STAGE (2 * A_HEX)
#define B_NB 66
#define B_HEX 1058
#define B_STAGE (2 * B_HEX)
#define GEMM_SMEM ((2 * A_STAGE + 2 * B_STAGE) * 4)   // 33376 bytes

struct BArgs {
    const float* resp[3];
    int aoff[3];
    int coff[3];
    int roff[3];
    int m[3];
    long long woff[3];
    int boff[3];
    int goff[3];
};

__global__ void __launch_bounds__(256) gemm_tc_kernel(
        const float* __restrict__ A, const float* __restrict__ W,
        float* __restrict__ C, int N, int K,
        const float* __restrict__ bias,
        const float* __restrict__ gate,
        int epi, BArgs ba) {
    int z = blockIdx.z;
    int brow = blockIdx.y, bcol = blockIdx.x;
    if (brow * TBM >= ba.m[z]) return;

    extern __shared__ uint32_t gsm[];
    uint32_t (*As)[A_STAGE] = (uint32_t(*)[A_STAGE])gsm;
    uint32_t (*Bs)[B_STAGE] = (uint32_t(*)[B_STAGE])(gsm + 2 * A_STAGE);

    int tid  = threadIdx.x;
    int warp = tid >> 5;
    int lane = tid & 31;
    int gid  = lane >> 2;
    int tig  = lane & 3;
    int wm4  = (warp >> 2) * 4;     // mblk base (0 or 4)
    int wn8  = (warp & 3) * 4;      // nblk base

    const float* Ab = A + (size_t)ba.aoff[z] * K;
    const float* Bb = W + ba.woff[z];

    // A tile 128x32 = 1024 float4 -> 4 per thread
    int a_row[4], abase[4];
    const float* Aptr[4];
    #pragma unroll
    for (int i = 0; i < 4; i++) {
        int al = tid + i * 256;
        a_row[i] = al >> 3;
        int a_kq = (al & 7) * 4;
        int kp = (a_kq >> 1) & 7, hex = a_kq >> 4;
        abase[i] = hex * A_HEX + (a_row[i] >> 4) * 128 + (a_row[i] & 7) * 16
                 + ((a_row[i] >> 3) & 1) * 2 + ((kp >> 2) & 1) + (kp & 3) * 4;
        Aptr[i] = Ab + (size_t)(brow * TBM + a_row[i]) * K + a_kq;
    }

    // B tile 32x128 = 2048 float2 -> 8 per thread
    int b_row = tid >> 6;
    int b_col = (tid & 63) * 2;
    int n7  = b_col & 7;
    int nbl = b_col >> 3;
    const float* Bptr = Bb + (size_t)b_row * N + bcol * TBN + b_col;

    float acc[4][4][4];
    #pragma unroll
    for (int i = 0; i < 4; i++)
        #pragma unroll
        for (int j = 0; j < 4; j++)
            #pragma unroll
            for (int c = 0; c < 4; c++) acc[i][j][c] = 0.f;

    int iters = K / TBK;

    float4 av[4];
    #pragma unroll
    for (int i = 0; i < 4; i++) av[i] = *(const float4*)(Aptr[i]);
    float2 bv[8];
    #pragma unroll
    for (int r = 0; r < 8; r++)
        bv[r] = *(const float2*)(Bptr + (size_t)(r * 4) * N);

    #define STORE_TILE(BUF) do {                                                     \
        _Pragma("unroll")                                                            \
        for (int i = 0; i < 4; i++) {                                                \
            As[BUF][abase[i]]     = pack_h2(av[i].x, av[i].y);                       \
            As[BUF][abase[i] + 4] = pack_h2(av[i].z, av[i].w);                       \
        }                                                                            \
        _Pragma("unroll")                                                            \
        for (int r = 0; r < 8; r++) {                                                \
            int k   = b_row + r * 4;                                                 \
            int hex = k >> 4;                                                        \
            int kp  = (k >> 1) & 7;                                                  \
            int sl  = (kp >> 2) & 1;                                                 \
            int jm  = kp & 3;                                                        \
            int par = k & 1;                                                         \
            uint32_t* bb = &Bs[BUF][hex * B_HEX + nbl * B_NB + sl];                  \
            ((__half*)&bb[(n7 * 4 + jm) * 2])[par]       = __float2half_rn(bv[r].x);\
            ((__half*)&bb[((n7 + 1) * 4 + jm) * 2])[par] = __float2half_rn(bv[r].y);\
        }                                                                            \
    } while (0)

    STORE_TILE(0);
    __syncthreads();

    for (int it = 0; it < iters; ++it) {
        int cur = it & 1;
        if (it + 1 < iters) {
            int k0 = (it + 1) * TBK;
            #pragma unroll
            for (int i = 0; i < 4; i++) av[i] = *(const float4*)(Aptr[i] + k0);
            #pragma unroll
            for (int r = 0; r < 8; r++)
                bv[r] = *(const float2*)(Bptr + (size_t)(k0 + r * 4) * N);
        }

        #pragma unroll
        for (int hex = 0; hex < 2; hex++) {
            uint4 ua[4];
            #pragma unroll
            for (int mt = 0; mt < 4; mt++)
                ua[mt] = *(const uint4*)&As[cur][hex * A_HEX + (wm4 + mt) * 128 + lane * 4];
            uint2 ub[4];
            #pragma unroll
            for (int nt = 0; nt < 4; nt++)
                ub[nt] = *(const uint2*)&Bs[cur][hex * B_HEX + (wn8 + nt) * B_NB + lane * 2];
            #pragma unroll
            for (int mt = 0; mt < 4; mt++)
                #pragma unroll
                for (int nt = 0; nt < 4; nt++)
                    mma_f16(acc[mt][nt][0], acc[mt][nt][1], acc[mt][nt][2], acc[mt][nt][3],
                            ua[mt].x, ua[mt].z, ua[mt].y, ua[mt].w,
                            ub[nt].x, ub[nt].y);
        }

        if (it + 1 < iters) {
            int nxt = cur ^ 1;
            STORE_TILE(nxt);
            __syncthreads();
        }
    }
    #undef STORE_TILE

    // epilogue
    int wm = (warp >> 2) * 64;
    int wn = (warp & 3) * 32;
    int crow = ba.coff[z];
    int rrow = ba.roff[z];
    const float* resz = ba.resp[z];
    int bo = ba.boff[z], go = ba.goff[z];
    #pragma unroll
    for (int mt = 0; mt < 4; mt++) {
        int lrow0 = brow * TBM + wm + mt * 16 + gid;
        int lrow1 = lrow0 + 8;
        #pragma unroll
        for (int nt = 0; nt < 4; nt++) {
            int col0 = bcol * TBN + wn + nt * 8 + tig * 2;
            int col1 = col0 + 1;
            float v0 = acc[mt][nt][0], v1 = acc[mt][nt][1];
            float v2 = acc[mt][nt][2], v3 = acc[mt][nt][3];
            if (epi == 1) {
                v0 = gelu_tanh(v0 + bias[bo + col0]); v1 = gelu_tanh(v1 + bias[bo + col1]);
                v2 = gelu_tanh(v2 + bias[bo + col0]); v3 = gelu_tanh(v3 + bias[bo + col1]);
            } else if (epi == 2) {
                v0 = resz[(size_t)(rrow + lrow0) * N + col0] + gate[go + col0] * (v0 + bias[bo + col0]);
                v1 = resz[(size_t)(rrow + lrow0) * N + col1] + gate[go + col1] * (v1 + bias[bo + col1]);
                v2 = resz[(size_t)(rrow + lrow1) * N + col0] + gate[go + col0] * (v2 + bias[bo + col0]);
                v3 = resz[(size_t)(rrow + lrow1) * N + col1] + gate[go + col1] * (v3 + bias[bo + col1]);
            }
            C[(size_t)(crow + lrow0) * N + col0] = v0;
            C[(size_t)(crow + lrow0) * N + col1] = v1;
            C[(size_t)(crow + lrow1) * N + col0] = v2;
            C[(size_t)(crow + lrow1) * N + col1] = v3;
        }
    }
}

// ---------------- QKV post: RMS + scale + RoPE + fp16 pack + scatter ----------------
__global__ void qkvpost_kernel(const float* __restrict__ Y, const float* __restrict__ pe,
                               const float* __restrict__ q_scale, const float* __restrict__ k_scale,
                               __half2* __restrict__ Q, __half2* __restrict__ K,
                               __half* __restrict__ V) {
    int gw = blockIdx.x * 8 + (threadIdx.x >> 5);
    int lane = threadIdx.x & 31;
    int l = gw >> 4;
    int h = gw & 15;
    int i = (l < L_TXT) ? 2 : (l < (L_TXT + L_IMG) ? 0 : 1);
    bool is_tmp = (l >= L_TXT + L_IMG);

    const float* row = Y + (size_t)l * 3072 + h * HD;
    float q0 = row[2 * lane],        q1 = row[2 * lane + 1];
    float k0 = row[1024 + 2 * lane], k1 = row[1024 + 2 * lane + 1];
    float v0 = row[2048 + 2 * lane], v1 = row[2048 + 2 * lane + 1];

    float qs = q0 * q0 + q1 * q1;
    float ks = k0 * k0 + k1 * k1;
    #pragma unroll
    for (int o = 16; o; o >>= 1) {
        qs += __shfl_xor_sync(0xffffffffu, qs, o);
        ks += __shfl_xor_sync(0xffffffffu, ks, o);
    }
    float qinv = rsqrtf(qs * (1.f / HD) + EPS);
    float kinv = rsqrtf(ks * (1.f / HD) + EPS);

    float qn0 = q0 * qinv * q_scale[i * HD + 2 * lane];
    float qn1 = q1 * qinv * q_scale[i * HD + 2 * lane + 1];
    float kn0 = k0 * kinv * k_scale[i * HD + 2 * lane];
    float kn1 = k1 * kinv * k_scale[i * HD + 2 * lane + 1];

    const float* p = pe + ((size_t)l * 32 + lane) * 4;
    float p00 = p[0], p01 = p[1], p10 = p[2], p11 = p[3];

    size_t w2 = ((size_t)h * L_ALL + l) * 32 + lane;
    Q[w2] = __floats2half2_rn((p00 * qn0 + p01 * qn1) * ATTN_SCALE,
                              (p10 * qn0 + p11 * qn1) * ATTN_SCALE);
    K[w2] = __floats2half2_rn(p00 * kn0 + p01 * kn1,
                              p10 * kn0 + p11 * kn1);
    float vo0, vo1;
    if (is_tmp) { vo0 = qn0; vo1 = qn1; }   // reference quirk
    else        { vo0 = v0;  vo1 = v1;  }
    size_t vbase = ((size_t)h * HD + 2 * lane) * L_ALL + l;
    V[vbase]         = __float2half_rn(vo0);
    V[vbase + L_ALL] = __float2half_rn(vo1);
}

// ---------------- flash attention, fp16 mma m16n8k16 (round-16 proven) ----------------
#define ATQ 64
#define ATK 64
#define ALD2 36
#define ATTN_SMEM (3 * 64 * ALD2 * 4)  // 27648 bytes

__global__ void __launch_bounds__(128) attn_tc_kernel(
        const __half* __restrict__ Q, const __half* __restrict__ K,
        const __half* __restrict__ V, float* __restrict__ Aout) {
    extern __shared__ uint32_t dyn[];
    uint32_t (*Ks)[ALD2] = (uint32_t(*)[ALD2])dyn;
    uint32_t (*Vt)[ALD2] = (uint32_t(*)[ALD2])(dyn + 64 * ALD2);
    uint32_t (*Ps)[ALD2] = (uint32_t(*)[ALD2])(dyn + 2 * 64 * ALD2);

    int h   = blockIdx.y;
    int q0  = blockIdx.x * ATQ;
    int tid = threadIdx.x;          // 128
    int warp = tid >> 5;
    int lane = tid & 31;
    int gid  = lane >> 2;
    int tig  = lane & 3;
    int w16  = warp * 16;

    const uint32_t* Qh = (const uint32_t*)(Q + (size_t)h * L_ALL * HD);
    const uint32_t* Kh = (const uint32_t*)(K + (size_t)h * L_ALL * HD);
    const uint32_t* Vh = (const uint32_t*)(V + (size_t)h * HD * L_ALL);

    #pragma unroll
    for (int i = 0; i < 4; i++) {
        int linear = tid + i * 128;
        int r = linear >> 3;
        int c4 = (linear & 7) * 4;
        uint4 qv = *(const uint4*)(Qh + (size_t)(q0 + r) * 32 + c4);
        *(uint4*)&Ps[r][c4] = qv;
    }
    __syncthreads();

    uint32_t qf[4][4];
    #pragma unroll
    for (int ks = 0; ks < 4; ks++) {
        qf[ks][0] = Ps[w16 + gid][ks * 8 + tig];
        qf[ks][1] = Ps[w16 + gid + 8][ks * 8 + tig];
        qf[ks][2] = Ps[w16 + gid][ks * 8 + tig + 4];
        qf[ks][3] = Ps[w16 + gid + 8][ks * 8 + tig + 4];
    }

    float oacc[8][4];
    #pragma unroll
    for (int nt = 0; nt < 8; nt++)
        #pragma unroll
        for (int c = 0; c < 4; c++) oacc[nt][c] = 0.f;
    float m0 = -INFINITY, m1 = -INFINITY, l0 = 0.f, l1 = 0.f;

    for (int kb = 0; kb < L_ALL; kb += ATK) {
        __syncthreads();
        #pragma unroll
        for (int i = 0; i < 4; i++) {
            int linear = tid + i * 128;
            int r = linear >> 3;
            int c4 = (linear & 7) * 4;
            uint4 kv = *(const uint4*)(Kh + (size_t)(kb + r) * 32 + c4);
            uint4 vv = *(const uint4*)(Vh + (size_t)r * (L_ALL / 2) + (kb >> 1) + c4);
            *(uint4*)&Ks[r][c4] = kv;
            *(uint4*)&Vt[r][c4] = vv;
        }
        __syncthreads();

        float sacc[8][4];
        #pragma unroll
        for (int nt = 0; nt < 8; nt++)
            #pragma unroll
            for (int c = 0; c < 4; c++) sacc[nt][c] = 0.f;
        #pragma unroll
        for (int ks = 0; ks < 4; ks++) {
            #pragma unroll
            for (int nt = 0; nt < 8; nt++) {
                uint32_t b0 = Ks[nt * 8 + gid][ks * 8 + tig];
                uint32_t b1 = Ks[nt * 8 + gid][ks * 8 + tig + 4];
                mma_f16(sacc[nt][0], sacc[nt][1], sacc[nt][2], sacc[nt][3],
                        qf[ks][0], qf[ks][1], qf[ks][2], qf[ks][3], b0, b1);
            }
        }

        float t0 = -INFINITY, t1 = -INFINITY;
        #pragma unroll
        for (int nt = 0; nt < 8; nt++) {
            t0 = fmaxf(t0, fmaxf(sacc[nt][0], sacc[nt][1]));
            t1 = fmaxf(t1, fmaxf(sacc[nt][2], sacc[nt][3]));
        }
        t0 = fmaxf(t0, __shfl_xor_sync(0xffffffffu, t0, 1));
        t0 = fmaxf(t0, __shfl_xor_sync(0xffffffffu, t0, 2));
        t1 = fmaxf(t1, __shfl_xor_sync(0xffffffffu, t1, 1));
        t1 = fmaxf(t1, __shfl_xor_sync(0xffffffffu, t1, 2));
        float mn0 = fmaxf(m0, t0), mn1 = fmaxf(m1, t1);
        float al0 = __expf(m0 - mn0), al1 = __expf(m1 - mn1);
        m0 = mn0; m1 = mn1;

        float ts0 = 0.f, ts1 = 0.f;
        #pragma unroll
        for (int nt = 0; nt < 8; nt++) {
            __half2 h0 = __floats2half2_rn(__expf(sacc[nt][0] - mn0), __expf(sacc[nt][1] - mn0));
            __half2 h1 = __floats2half2_rn(__expf(sacc[nt][2] - mn1), __expf(sacc[nt][3] - mn1));
            Ps[w16 + gid][nt * 4 + tig]     = *(uint32_t*)&h0;
            Ps[w16 + gid + 8][nt * 4 + tig] = *(uint32_t*)&h1;
            float2 f0 = __half22float2(h0), f1 = __half22float2(h1);
            ts0 += f0.x + f0.y;
            ts1 += f1.x + f1.y;
        }
        ts0 += __shfl_xor_sync(0xffffffffu, ts0, 1);
        ts0 += __shfl_xor_sync(0xffffffffu, ts0, 2);
        ts1 += __shfl_xor_sync(0xffffffffu, ts1, 1);
        ts1 += __shfl_xor_sync(0xffffffffu, ts1, 2);
        l0 = l0 * al0 + ts0;
        l1 = l1 * al1 + ts1;

        #pragma unroll
        for (int nt = 0; nt < 8; nt++) {
            oacc[nt][0] *= al0; oacc[nt][1] *= al0;
            oacc[nt][2] *= al1; oacc[nt][3] *= al1;
        }
        __syncwarp();

        #pragma unroll
        for (int ks = 0; ks < 4; ks++) {
            uint32_t a0 = Ps[w16 + gid][ks * 8 + tig];
            uint32_t a1 = Ps[w16 + gid + 8][ks * 8 + tig];
            uint32_t a2 = Ps[w16 + gid][ks * 8 + tig + 4];
            uint32_t a3 = Ps[w16 + gid + 8][ks * 8 + tig + 4];
            #pragma unroll
            for (int nt = 0; nt < 8; nt++) {
                uint32_t b0 = Vt[nt * 8 + gid][ks * 8 + tig];
                uint32_t b1 = Vt[nt * 8 + gid][ks * 8 + tig + 4];
                mma_f16(oacc[nt][0], oacc[nt][1], oacc[nt][2], oacc[nt][3],
                        a0, a1, a2, a3, b0, b1);
            }
        }
        __syncwarp();
    }

    float i0 = 1.f / l0, i1 = 1.f / l1;
    int r0 = q0 + w16 + gid;
    int r1 = r0 + 8;
    #pragma unroll
    for (int nt = 0; nt < 8; nt++) {
        int c0 = h * HD + nt * 8 + tig * 2;
        Aout[(size_t)r0 * D_MODEL + c0]     = oacc[nt][0] * i0;
        Aout[(size_t)r0 * D_MODEL + c0 + 1] = oacc[nt][1] * i0;
        Aout[(size_t)r1 * D_MODEL + c0]     = oacc[nt][2] * i1;
        Aout[(size_t)r1 * D_MODEL + c0 + 1] = oacc[nt][3] * i1;
    }
}

extern "C" void kernel_launch(void* const* d_in, const int* in_sizes, int n_in,
                              void* d_out, int out_size) {
    const float* img      = (const float*)d_in[0];
    const float* temporal = (const float*)d_in[1];
    const float* txt      = (const float*)d_in[2];
    const float* vec      = (const float*)d_in[3];
    const float* pe       = (const float*)d_in[4];
    const float* mod_w    = (const float*)d_in[5];
    const float* mod_b    = (const float*)d_in[6];
    const float* qkv_w    = (const float*)d_in[7];
    const float* q_scale  = (const float*)d_in[8];
    const float* k_scale  = (const float*)d_in[9];
    const float* proj_w   = (const float*)d_in[10];
    const float* proj_b   = (const float*)d_in[11];
    const float* mlp_w1   = (const float*)d_in[12];
    const float* mlp_b1   = (const float*)d_in[13];
    const float* mlp_w2   = (const float*)d_in[14];
    const float* mlp_b2   = (const float*)d_in[15];
    float* out = (float*)d_out;

    static float *mod = 0, *xm = 0, *qkv = 0, *attn = 0, *x1 = 0, *ym = 0, *hbuf = 0;
    static __half *Qb = 0, *Kb = 0, *Vb = 0;
    if (!mod) {
        cudaGetSymbolAddress((void**)&mod,  g_mod);
        cudaGetSymbolAddress((void**)&xm,   g_xm);
        cudaGetSymbolAddress((void**)&qkv,  g_qkv);
        cudaGetSymbolAddress((void**)&Qb,   g_Q);
        cudaGetSymbolAddress((void**)&Kb,   g_K);
        cudaGetSymbolAddress((void**)&Vb,   g_V);
        cudaGetSymbolAddress((void**)&attn, g_attn);
        cudaGetSymbolAddress((void**)&x1,   g_x1);
        cudaGetSymbolAddress((void**)&ym,   g_ym);
        cudaGetSymbolAddress((void**)&hbuf, g_h);
        cudaFuncSetAttribute(attn_tc_kernel,
                             cudaFuncAttributeMaxDynamicSharedMemorySize, ATTN_SMEM);
        cudaFuncSetAttribute(gemm_tc_kernel,
                             cudaFuncAttributeMaxDynamicSharedMemorySize, GEMM_SMEM);
    }

    const int off_txt = 0;
    const int off_img = L_TXT;
    const int off_tmp = L_TXT + L_IMG;

    // 1. mod (silu fused)
    mod_kernel<<<(3 * 6144) / 256, 256>>>(vec, mod_w, mod_b, mod);

    // 2. LN1 + modulate
    lnmod_kernel<<<L_TXT, 256>>>(txt,      xm + (size_t)off_txt * D_MODEL, mod + 2 * 6144, mod + 2 * 6144 + 1024);
    lnmod_kernel<<<L_IMG, 256>>>(img,      xm + (size_t)off_img * D_MODEL, mod + 0,        mod + 1024);
    lnmod_kernel<<<L_TMP, 256>>>(temporal, xm + (size_t)off_tmp * D_MODEL, mod + 1 * 6144, mod + 1 * 6144 + 1024);

    // 3. QKV (batched z=3: txt->w2, img->w0, tmp->w1)
    {
        BArgs ba = {};
        int ao[3] = {off_txt, off_img, off_tmp};
        for (int z = 0; z < 3; z++) { ba.aoff[z] = ao[z]; ba.coff[z] = ao[z]; }
        ba.m[0] = 256; ba.m[1] = 1024; ba.m[2] = 1024;
        ba.woff[0] = 2LL * 1024 * 3072; ba.woff[1] = 0; ba.woff[2] = 1LL * 1024 * 3072;
        gemm_tc_kernel<<<dim3(3072 / TBN, 8, 3), 256, GEMM_SMEM>>>(xm, qkv_w, qkv, 3072, 1024,
                                                                   proj_b, mod, 0, ba);
    }

    // 4. RMS + scale + RoPE + fp16 pack + scatter
    qkvpost_kernel<<<(L_ALL * NH) / 8, 256>>>(qkv, pe, q_scale, k_scale,
                                              (__half2*)Qb, (__half2*)Kb, Vb);

    // 5. attention (fp16 mma)
    attn_tc_kernel<<<dim3(L_ALL / ATQ, NH), 128, ATTN_SMEM>>>(Qb, Kb, Vb, attn);

    // 6. proj + gate + residual (batched z=3)
    {
        BArgs ba = {};
        int ao[3] = {off_txt, off_img, off_tmp};
        int wi[3] = {2, 0, 1};
        const float* rp[3] = {txt, img, temporal};
        for (int z = 0; z < 3; z++) {
            ba.aoff[z] = ao[z]; ba.coff[z] = ao[z]; ba.roff[z] = 0;
            ba.resp[z] = rp[z];
            ba.woff[z] = (long long)wi[z] * 1024 * 1024;
            ba.boff[z] = wi[z] * 1024;
            ba.goff[z] = wi[z] * 6144 + 2048;
        }
        ba.m[0] = 256; ba.m[1] = 1024; ba.m[2] = 1024;
        gemm_tc_kernel<<<dim3(1024 / TBN, 8, 3), 256, GEMM_SMEM>>>(attn, proj_w, x1, 1024, 1024,
                                                                   proj_b, mod, 2, ba);
    }

    // 7. img + txt MLP (batched z=2); temporal must wait for final img
    lnmod_kernel<<<L_IMG, 256>>>(x1 + (size_t)off_img * D_MODEL, ym,
                                 mod + 0 * 6144 + 3072, mod + 0 * 6144 + 4096);
    lnmod_kernel<<<L_TXT, 256>>>(x1 + (size_t)off_txt * D_MODEL, ym + (size_t)1024 * D_MODEL,
                                 mod + 2 * 6144 + 3072, mod + 2 * 6144 + 4096);
    {
        BArgs ba = {};
        ba.aoff[0] = 0;    ba.coff[0] = 0;    ba.m[0] = 1024;
        ba.woff[0] = 0;    ba.boff[0] = 0;
        ba.aoff[1] = 1024; ba.coff[1] = 1024; ba.m[1] = 256;
        ba.woff[1] = 2LL * 1024 * 4096; ba.boff[1] = 2 * 4096;
        gemm_tc_kernel<<<dim3(4096 / TBN, 8, 2), 256, GEMM_SMEM>>>(ym, mlp_w1, hbuf, 4096, 1024,
                                                                   mlp_b1, mod, 1, ba);
    }
    {
        BArgs ba = {};
        ba.aoff[0] = 0;    ba.coff[0] = 0;    ba.roff[0] = off_img; ba.resp[0] = x1; ba.m[0] = 1024;
        ba.woff[0] = 0;    ba.boff[0] = 0;    ba.goff[0] = 0 * 6144 + 5120;
        ba.aoff[1] = 1024; ba.coff[1] = 2048; ba.roff[1] = off_txt; ba.resp[1] = x1; ba.m[1] = 256;
        ba.woff[1] = 2LL * 4096 * 1024; ba.boff[1] = 2 * 1024; ba.goff[1] = 2 * 6144 + 5120;
        gemm_tc_kernel<<<dim3(1024 / TBN, 8, 2), 256, GEMM_SMEM>>>(hbuf, mlp_w2, out, 1024, 4096,
                                                                   mlp_b2, mod, 2, ba);
    }

    // 8. temporal MLP: LN of FINAL img (reference quirk), residual = x1 tmp rows
    lnmod_kernel<<<L_TMP, 256>>>(out, ym, mod + 1 * 6144 + 3072, mod + 1 * 6144 + 4096);
    {
        BArgs ba = {};
        ba.aoff[0] = 0; ba.coff[0] = 0; ba.m[0] = 1024;
        ba.woff[0] = 1LL * 1024 * 4096; ba.boff[0] = 4096;
        gemm_tc_kernel<<<dim3(4096 / TBN, 8, 1), 256, GEMM_SMEM>>>(ym, mlp_w1, hbuf, 4096, 1024,
                                                                   mlp_b1, mod, 1, ba);
    }
    {
        BArgs ba = {};
        ba.aoff[0] = 0; ba.coff[0] = 1024; ba.roff[0] = off_tmp; ba.resp[0] = x1; ba.m[0] = 1024;
        ba.woff[0] = 1LL * 4096 * 1024; ba.boff[0] = 1024; ba.goff[0] = 1 * 6144 + 5120;
        gemm_tc_kernel<<<dim3(1024 / TBN, 8, 1), 256, GEMM_SMEM>>>(hbuf, mlp_w2, out, 1024, 4096,
                                                                   mlp_b2, mod, 2, ba);
    }
}